// round 10
// baseline (speedup 1.0000x reference)
#include <cuda_runtime.h>
#include <math.h>

#define MAXN 32768
#define NBKT 32

#define FADD __fadd_rn
#define FSUB __fsub_rn
#define FMUL __fmul_rn
#define FDIV __fdiv_rn

#define EPSF   5.9604644775390625e-08f     // 2^-24
#define EPS2F  (EPSF * EPSF)
#define SAFMINF 1.1754943508222875e-38f    // 2^-126

// Scratch (device globals; no allocation).
__device__ float4 g_pos4[MAXN];
__device__ float4 g_t0[MAXN];          // d1,d2,d3,e1
__device__ float4 g_t1[MAXN];          // e2,tau1,v3,flag
__device__ unsigned char g_key[MAXN];
__device__ int g_cnt[NBKT];
__device__ int g_off[NBKT];
__device__ int g_order[MAXN];

// ---------------------------------------------------------------------------
// Kernel 1: pad positions + zero bucket counters.
// ---------------------------------------------------------------------------
__global__ void pad_kernel(const float* __restrict__ pos, int n) {
    int i = blockIdx.x * blockDim.x + threadIdx.x;
    if (i < NBKT) g_cnt[i] = 0;
    if (i >= n) return;
    float4 p;
    p.x = pos[3 * i + 0];
    p.y = pos[3 * i + 1];
    p.z = pos[3 * i + 2];
    p.w = 0.f;
    g_pos4[i] = p;
}

// ---------------------------------------------------------------------------
// LAPACK fp32 helpers, netlib-expression-faithful (LAPACK >= 3.10).
// FROZEN: arithmetic validated at rel_err 3.4e-7 — do not reorder.
// ---------------------------------------------------------------------------
__device__ __forceinline__ float slapy2f(float x, float y) {
    float xa = fabsf(x), ya = fabsf(y);
    float w = fmaxf(xa, ya), z = fminf(xa, ya);
    if (z == 0.f) return w;
    float t = FDIV(z, w);
    return FMUL(w, sqrtf(FADD(1.f, FMUL(t, t))));
}

__device__ __forceinline__ void slartgf(float f, float g, float& c, float& s,
                                        float& r) {
    if (g == 0.f) {
        c = 1.f; s = 0.f; r = f;
    } else if (f == 0.f) {
        c = 0.f; s = copysignf(1.f, g); r = fabsf(g);
    } else {
        float d = sqrtf(FADD(FMUL(f, f), FMUL(g, g)));
        float p = FDIV(1.f, d);
        c = FMUL(fabsf(f), p);
        s = FMUL(g, copysignf(p, f));
        r = copysignf(d, f);
    }
}

__device__ void slaev2f(float a, float b, float c0, float& rt1, float& rt2,
                        float& cs1, float& sn1) {
    float sm = FADD(a, c0);
    float df = FSUB(a, c0);
    float adf = fabsf(df);
    float tb = FADD(b, b);
    float ab = fabsf(tb);
    float acmx, acmn;
    if (fabsf(a) > fabsf(c0)) { acmx = a; acmn = c0; }
    else { acmx = c0; acmn = a; }
    float rt;
    if (adf > ab) {
        float t = FDIV(ab, adf);
        rt = FMUL(adf, sqrtf(FADD(1.f, FMUL(t, t))));
    } else if (adf < ab) {
        float t = FDIV(adf, ab);
        rt = FMUL(ab, sqrtf(FADD(1.f, FMUL(t, t))));
    } else {
        rt = FMUL(ab, sqrtf(2.f));
    }
    int sgn1;
    if (sm < 0.f) {
        rt1 = FMUL(0.5f, FSUB(sm, rt)); sgn1 = -1;
        rt2 = FSUB(FMUL(FDIV(acmx, rt1), acmn), FMUL(FDIV(b, rt1), b));
    } else if (sm > 0.f) {
        rt1 = FMUL(0.5f, FADD(sm, rt)); sgn1 = 1;
        rt2 = FSUB(FMUL(FDIV(acmx, rt1), acmn), FMUL(FDIV(b, rt1), b));
    } else {
        rt1 = FMUL(0.5f, rt); rt2 = FMUL(-0.5f, rt); sgn1 = 1;
    }
    int sgn2;
    float cs;
    if (df >= 0.f) { cs = FADD(df, rt); sgn2 = 1; }
    else { cs = FSUB(df, rt); sgn2 = -1; }
    float acs = fabsf(cs);
    if (acs > ab) {
        float ct = FDIV(-tb, cs);
        sn1 = FDIV(1.f, sqrtf(FADD(1.f, FMUL(ct, ct))));
        cs1 = FMUL(ct, sn1);
    } else {
        if (ab == 0.f) { cs1 = 1.f; sn1 = 0.f; }
        else {
            float tn = FDIV(-cs, tb);
            cs1 = FDIV(1.f, sqrtf(FADD(1.f, FMUL(tn, tn))));
            sn1 = FMUL(tn, cs1);
        }
    }
    if (sgn1 == sgn2) { float tau = cs1; cs1 = -sn1; sn1 = tau; }
}

// Register-resident index helpers.
__device__ __forceinline__ float sel3(int i, float v1, float v2, float v3) {
    return i == 1 ? v1 : (i == 2 ? v2 : v3);
}
__device__ __forceinline__ float sel2(int i, float v1, float v2) {
    return i == 1 ? v1 : v2;
}
#define SETD(i, x) do { float _x = (x); if ((i) == 1) d1 = _x; \
                        else if ((i) == 2) d2 = _x; else d3 = _x; } while (0)
#define SETE(i, x) do { float _x = (x); if ((i) == 1) e1 = _x; \
                        else e2 = _x; } while (0)

#define ROT12(c, s) do { float _t; \
    _t = z12; z12 = FSUB(FMUL(c, _t), FMUL(s, z11)); z11 = FADD(FMUL(s, _t), FMUL(c, z11)); \
    _t = z22; z22 = FSUB(FMUL(c, _t), FMUL(s, z21)); z21 = FADD(FMUL(s, _t), FMUL(c, z21)); \
    _t = z32; z32 = FSUB(FMUL(c, _t), FMUL(s, z31)); z31 = FADD(FMUL(s, _t), FMUL(c, z31)); \
} while (0)
#define ROT23(c, s) do { float _t; \
    _t = z13; z13 = FSUB(FMUL(c, _t), FMUL(s, z12)); z12 = FADD(FMUL(s, _t), FMUL(c, z12)); \
    _t = z23; z23 = FSUB(FMUL(c, _t), FMUL(s, z22)); z22 = FADD(FMUL(s, _t), FMUL(c, z22)); \
    _t = z33; z33 = FSUB(FMUL(c, _t), FMUL(s, z32)); z32 = FADD(FMUL(s, _t), FMUL(c, z32)); \
} while (0)
#define MROTA(c, s) do { float _t; \
    _t = z11; z11 = FSUB(FMUL(c, _t), FMUL(s, z12)); z12 = FADD(FMUL(s, _t), FMUL(c, z12)); \
    _t = z21; z21 = FSUB(FMUL(c, _t), FMUL(s, z22)); z22 = FADD(FMUL(s, _t), FMUL(c, z22)); \
    _t = z31; z31 = FSUB(FMUL(c, _t), FMUL(s, z32)); z32 = FADD(FMUL(s, _t), FMUL(c, z32)); \
} while (0)
#define MROTB(c, s) do { float _t; \
    _t = z12; z12 = FSUB(FMUL(c, _t), FMUL(s, z13)); z13 = FADD(FMUL(s, _t), FMUL(c, z13)); \
    _t = z22; z22 = FSUB(FMUL(c, _t), FMUL(s, z23)); z23 = FADD(FMUL(s, _t), FMUL(c, z23)); \
    _t = z32; z32 = FSUB(FMUL(c, _t), FMUL(s, z33)); z33 = FADD(FMUL(s, _t), FMUL(c, z33)); \
} while (0)
#define SWAPC12() do { float _t; _t = z11; z11 = z12; z12 = _t; \
    _t = z21; z21 = z22; z22 = _t; _t = z31; z31 = z32; z32 = _t; } while (0)
#define SWAPC13() do { float _t; _t = z11; z11 = z13; z13 = _t; \
    _t = z21; z21 = z23; z23 = _t; _t = z31; z31 = z33; z33 = _t; } while (0)
#define SWAPC23() do { float _t; _t = z12; z12 = z13; z13 = _t; \
    _t = z22; z22 = z23; z23 = _t; _t = z32; z32 = z33; z33 = _t; } while (0)

__device__ __forceinline__ void cov_acc(float4 q, float px, float py, float pz,
                                        float& a00, float& a10, float& a20,
                                        float& a11, float& a21, float& a22) {
    float dx = FSUB(q.x, px);
    float dy = FSUB(q.y, py);
    float dz = FSUB(q.z, pz);
    a00 = FADD(a00, FMUL(dx, dx));
    a10 = FADD(a10, FMUL(dx, dy));
    a20 = FADD(a20, FMUL(dx, dz));
    a11 = FADD(a11, FMUL(dy, dy));
    a21 = FADD(a21, FMUL(dy, dz));
    a22 = FADD(a22, FMUL(dz, dz));
}

// Deflation test (key heuristic; matches solver's test, perf-only if wrong).
__device__ __forceinline__ bool small_e(float e, float da, float db) {
    float t = fabsf(e);
    if (t == 0.f) return true;
    return t <= FMUL(FMUL(sqrtf(fabsf(da)), sqrtf(fabsf(db))), EPSF);
}
__device__ __forceinline__ bool small_e2(float e, float da, float db) {
    float t = FMUL(e, e);
    return t <= FADD(FMUL(FMUL(EPS2F, fabsf(da)), fabsf(db)), SAFMINF);
}

// ---------------------------------------------------------------------------
// Kernel 2: cov + ssytd2 (frozen) -> scratch; path-key -> bucket count.
// ---------------------------------------------------------------------------
__global__ void __launch_bounds__(128, 1)
covtrid_kernel(const int* __restrict__ edge_src,
               const int* __restrict__ num_neighbors,
               float* __restrict__ out, int n, int k) {
    int gi = blockIdx.x * blockDim.x + threadIdx.x;
    if (gi >= n) return;

    if (num_neighbors[gi] <= 1) {
        float* o = out + (long long)gi * 9;
#pragma unroll
        for (int j = 0; j < 9; j++) o[j] = 0.f;
        g_t1[gi] = make_float4(0.f, 0.f, 0.f, 1.f);
        g_key[gi] = 0;
        atomicAdd(&g_cnt[0], 1);
        return;
    }

    // ================= covariance (frozen arithmetic order) ==============
    float4 pc = g_pos4[gi];
    float px = pc.x, py = pc.y, pz = pc.z;
    float a00 = 0.f, a10 = 0.f, a20 = 0.f, a11 = 0.f, a21 = 0.f, a22 = 0.f;
    const int4* es4 = (const int4*)(edge_src + (long long)gi * k);
#pragma unroll 8
    for (int j = 0; j < k / 4; j++) {
        int4 s4 = es4[j];
        float4 q0 = __ldg(&g_pos4[s4.x]);
        float4 q1 = __ldg(&g_pos4[s4.y]);
        float4 q2 = __ldg(&g_pos4[s4.z]);
        float4 q3 = __ldg(&g_pos4[s4.w]);
        cov_acc(q0, px, py, pz, a00, a10, a20, a11, a21, a22);
        cov_acc(q1, px, py, pz, a00, a10, a20, a11, a21, a22);
        cov_acc(q2, px, py, pz, a00, a10, a20, a11, a21, a22);
        cov_acc(q3, px, py, pz, a00, a10, a20, a11, a21, a22);
    }

    // ================= SSYTD2 (lower), n=3 — FROZEN =================
    float d1, d2, d3, e1, e2;
    float tau1 = 0.f, v3 = 0.f;
    {
        float alpha = a10;
        float x = a20;
        if (x == 0.f) {
            tau1 = 0.f;
            e1 = alpha;
        } else {
            float beta = -copysignf(slapy2f(alpha, x), alpha);
            tau1 = FDIV(FSUB(beta, alpha), beta);
            float rcp = FDIV(1.f, FSUB(alpha, beta));
            v3 = FMUL(x, rcp);
            e1 = beta;
            float w1 = FADD(FMUL(tau1, a11), FMUL(tau1, FMUL(a21, v3)));
            float w2 = FADD(FMUL(tau1, a21), FMUL(FMUL(tau1, v3), a22));
            float dot = FADD(w1, FMUL(w2, v3));
            float al2 = -FMUL(FMUL(0.5f, tau1), dot);
            w1 = FADD(w1, al2);
            w2 = FADD(w2, FMUL(al2, v3));
            a11 = FADD(FADD(a11, -w1), -w1);
            a21 = FADD(FADD(a21, FMUL(v3, -w1)), -w2);
            a22 = FADD(FADD(a22, FMUL(v3, -w2)), FMUL(w2, -v3));
        }
        e2 = a21;
        d1 = a00; d2 = a11; d3 = a22;
    }

    g_t0[gi] = make_float4(d1, d2, d3, e1);
    g_t1[gi] = make_float4(e2, tau1, v3, 0.f);

    // ================= path key (scheduling only) =================
    int m = 3;
    if (small_e(e1, d1, d2)) m = 1;
    else if (small_e(e2, d2, d3)) m = 2;

    int ql, cse;
    if (m == 1) {
        if (small_e(e2, d2, d3)) {
            ql = 0; cse = 3;            // fully deflated
        } else {
            ql = (fabsf(d3) < fabsf(d2)) ? 0 : 1;
            cse = small_e2(e2, ql ? d2 : d3, ql ? d3 : d2) ? 0 : 1;
        }
    } else if (m == 2) {
        ql = (fabsf(d2) < fabsf(d1)) ? 0 : 1;
        cse = small_e2(e1, ql ? d1 : d2, ql ? d2 : d1) ? 0 : 1;
    } else {
        ql = (fabsf(d3) < fabsf(d1)) ? 0 : 1;
        if (ql) {
            if (small_e2(e1, d1, d2)) cse = 0;
            else if (small_e2(e2, d2, d3)) cse = 1;
            else cse = 2;
        } else {
            if (small_e2(e2, d3, d2)) cse = 0;
            else if (small_e2(e1, d2, d1)) cse = 1;
            else cse = 2;
        }
    }
    int key = 1 + ((m - 1) << 3) + (ql << 2) + cse;   // 1..27 < NBKT
    g_key[gi] = (unsigned char)key;
    atomicAdd(&g_cnt[key], 1);
}

// ---------------------------------------------------------------------------
// Kernel 3: exclusive scan of 32 bucket counts (1 thread).
// ---------------------------------------------------------------------------
__global__ void scan_kernel() {
    if (threadIdx.x == 0 && blockIdx.x == 0) {
        int run = 0;
        for (int b = 0; b < NBKT; b++) {
            g_off[b] = run;
            run += g_cnt[b];
        }
    }
}

// ---------------------------------------------------------------------------
// Kernel 4: scatter node ids into bucket order.
// ---------------------------------------------------------------------------
__global__ void scatter_kernel(int n) {
    int i = blockIdx.x * blockDim.x + threadIdx.x;
    if (i >= n) return;
    int pos = atomicAdd(&g_off[g_key[i]], 1);
    g_order[pos] = i;
}

// ---------------------------------------------------------------------------
// Kernel 5: ssteqr('I') + sormtr per node, bucket-sorted (path-homogeneous
// warps). Solver arithmetic FROZEN (identical to validated R9 code).
// ---------------------------------------------------------------------------
__global__ void __launch_bounds__(128, 1)
eig_kernel(float* __restrict__ out, int n) {
    int tid = blockIdx.x * blockDim.x + threadIdx.x;
    if (tid >= n) return;
    int gi = g_order[tid];

    float4 t0 = g_t0[gi];
    float4 t1 = g_t1[gi];
    if (t1.w != 0.f) return;    // zero-neighbor node: out already written

    float d1 = t0.x, d2 = t0.y, d3 = t0.z, e1 = t0.w;
    float e2 = t1.x, tau1 = t1.y, v3 = t1.z;

    const float eps = EPSF;
    const float eps2 = FMUL(eps, eps);
    const float safmin = SAFMINF;
    const int nmaxit = 90;
    int jtot = 0;

    float z11 = 1.f, z21 = 0.f, z31 = 0.f;
    float z12 = 0.f, z22 = 1.f, z32 = 0.f;
    float z13 = 0.f, z23 = 0.f, z33 = 1.f;

    int l1 = 1;
    while (l1 <= 3) {
        if (l1 > 1) SETE(l1 - 1, 0.f);
        int m = 3;
        for (int mm = l1; mm <= 2; mm++) {
            float tst = fabsf(sel2(mm, e1, e2));
            if (tst == 0.f) { m = mm; break; }
            if (tst <= FMUL(FMUL(sqrtf(fabsf(sel3(mm, d1, d2, d3))),
                                 sqrtf(fabsf(sel3(mm + 1, d1, d2, d3)))),
                            eps)) {
                SETE(mm, 0.f);
                m = mm; break;
            }
        }
        int l = l1, lsv = l, lend = m, lendsv = lend;
        l1 = m + 1;
        if (lend == l) continue;

        float anorm = 0.f;
        for (int i = l; i <= lend; i++)
            anorm = fmaxf(anorm, fabsf(sel3(i, d1, d2, d3)));
        for (int i = l; i <= lend - 1; i++)
            anorm = fmaxf(anorm, fabsf(sel2(i, e1, e2)));
        if (anorm == 0.f) continue;

        if (fabsf(sel3(lend, d1, d2, d3)) < fabsf(sel3(l, d1, d2, d3))) {
            lend = lsv; l = lendsv;
        }

        bool ql = (lend > l);
        int lv = ql ? l : 4 - l;
        int lendv = ql ? lend : 4 - lend;

        while (1) {
            int m2 = lendv;
            if (lv != lendv) {
                for (int mm = lv; mm <= lendv - 1; mm++) {
                    float emm = sel2(ql ? mm : 3 - mm, e1, e2);
                    float tst = FMUL(emm, emm);
                    float dmm = sel3(ql ? mm : 4 - mm, d1, d2, d3);
                    float dmm1 = sel3(ql ? mm + 1 : 3 - mm, d1, d2, d3);
                    if (tst <= FADD(FMUL(FMUL(eps2, fabsf(dmm)), fabsf(dmm1)),
                                    safmin)) {
                        m2 = mm; break;
                    }
                }
            }
            if (m2 < lendv) SETE(ql ? m2 : 3 - m2, 0.f);
            float p = sel3(ql ? lv : 4 - lv, d1, d2, d3);
            if (m2 == lv) {
                lv = lv + 1;
                if (lv <= lendv) continue;
                break;
            }
            if (m2 == lv + 1) {
                float rt1, rt2, c, s;
                float bb = sel2(ql ? lv : 3 - lv, e1, e2);
                float aa, cc;
                if (ql) {
                    aa = sel3(lv, d1, d2, d3);
                    cc = sel3(lv + 1, d1, d2, d3);
                } else {
                    aa = sel3(3 - lv, d1, d2, d3);
                    cc = sel3(4 - lv, d1, d2, d3);
                }
                slaev2f(aa, bb, cc, rt1, rt2, c, s);
                if ((ql && lv == 1) || (!ql && lv == 2)) { ROT12(c, s); }
                else { ROT23(c, s); }
                if (ql) {
                    SETD(lv, rt1); SETD(lv + 1, rt2); SETE(lv, 0.f);
                } else {
                    SETD(3 - lv, rt1); SETD(4 - lv, rt2); SETE(3 - lv, 0.f);
                }
                lv = lv + 2;
                if (lv <= lendv) continue;
                break;
            }
            if (jtot == nmaxit) break;
            jtot++;
            float vd1 = ql ? d1 : d3, vd3 = ql ? d3 : d1;
            float ve1 = ql ? e1 : e2, ve2 = ql ? e2 : e1;
            float g = FDIV(FSUB(d2, p), FMUL(2.f, ve1));
            float r = slapy2f(g, 1.f);
            g = FADD(FSUB(vd3, p), FDIV(ve1, FADD(g, copysignf(r, g))));
            float s = 1.f, c = 1.f;
            p = 0.f;
            float wc1, wc2, ws1, ws2;
            {   // virtual i = 2
                float f = FMUL(s, ve2);
                float b = FMUL(c, ve2);
                slartgf(g, f, c, s, r);
                g = FSUB(vd3, p);
                r = FADD(FMUL(FSUB(d2, g), s), FMUL(FMUL(2.f, c), b));
                p = FMUL(s, r);
                vd3 = FADD(g, p);
                g = FSUB(FMUL(c, r), b);
                wc2 = c; ws2 = -s;
            }
            {   // virtual i = 1
                float f = FMUL(s, ve1);
                float b = FMUL(c, ve1);
                slartgf(g, f, c, s, r);
                ve2 = r;
                g = FSUB(d2, p);
                r = FADD(FMUL(FSUB(vd1, g), s), FMUL(FMUL(2.f, c), b));
                p = FMUL(s, r);
                d2 = FADD(g, p);
                g = FSUB(FMUL(c, r), b);
                wc1 = c; ws1 = -s;
            }
            if (wc2 != 1.f || ws2 != 0.f) {
                if (ql) { ROT23(wc2, ws2); } else { MROTA(wc2, ws2); }
            }
            if (wc1 != 1.f || ws1 != 0.f) {
                if (ql) { ROT12(wc1, ws1); } else { MROTB(wc1, ws1); }
            }
            vd1 = FSUB(vd1, p);
            ve1 = g;
            if (ql) { d1 = vd1; d3 = vd3; e1 = ve1; e2 = ve2; }
            else    { d3 = vd1; d1 = vd3; e2 = ve1; e1 = ve2; }
        }
    }

    // selection sort (ascending, column swaps)
    {
        int kk = 1; float p = d1;
        if (d2 < p) { kk = 2; p = d2; }
        if (d3 < p) { kk = 3; p = d3; }
        if (kk == 2) { d2 = d1; d1 = p; SWAPC12(); }
        else if (kk == 3) { d3 = d1; d1 = p; SWAPC13(); }
    }
    {
        if (d3 < d2) { float p = d2; d2 = d3; d3 = p; SWAPC23(); }
    }

    // SORMTR: Z := H(1)*Z
    if (tau1 != 0.f) {
        float w, t;
        w = FADD(z21, FMUL(z31, v3)); t = FMUL(-tau1, w);
        z21 = FADD(z21, t); z31 = FADD(z31, FMUL(v3, t));
        w = FADD(z22, FMUL(z32, v3)); t = FMUL(-tau1, w);
        z22 = FADD(z22, t); z32 = FADD(z32, FMUL(v3, t));
        w = FADD(z23, FMUL(z33, v3)); t = FMUL(-tau1, w);
        z23 = FADD(z23, t); z33 = FADD(z33, FMUL(v3, t));
    }

    float* o = out + (long long)gi * 9;
    o[0] = z11; o[1] = z21; o[2] = z31;
    o[3] = z12; o[4] = z22; o[5] = z32;
    o[6] = z13; o[7] = z23; o[8] = z33;
}

// ---------------------------------------------------------------------------
// Launch
// ---------------------------------------------------------------------------
extern "C" void kernel_launch(void* const* d_in, const int* in_sizes, int n_in,
                              void* d_out, int out_size) {
    const float* pos = (const float*)d_in[0];
    const int* edge_src = (const int*)d_in[1];
    // d_in[2] = edge_dst: unused (edge_dst == repeat(arange(n), k))
    const int* num_neighbors = (const int*)d_in[3];

    int n = in_sizes[3];
    int k = in_sizes[1] / n;

    pad_kernel<<<(n + 255) / 256, 256>>>(pos, n);
    covtrid_kernel<<<(n + 127) / 128, 128>>>(edge_src, num_neighbors,
                                             (float*)d_out, n, k);
    scan_kernel<<<1, 32>>>();
    scatter_kernel<<<(n + 255) / 256, 256>>>(n);
    eig_kernel<<<(n + 127) / 128, 128>>>((float*)d_out, n);
}

// round 11
// speedup vs baseline: 1.7018x; 1.7018x over previous
#include <cuda_runtime.h>
#include <math.h>

#define MAXN 32768
#define NBKT 32

#define FADD __fadd_rn
#define FSUB __fsub_rn
#define FMUL __fmul_rn
#define FDIV __fdiv_rn

#define EPSF   5.9604644775390625e-08f     // 2^-24
#define EPS2F  (EPSF * EPSF)
#define SAFMINF 1.1754943508222875e-38f    // 2^-126

// Scratch (device globals; no allocation).
__device__ float4 g_pos4[MAXN];
__device__ float4 g_t0[MAXN];          // d1,d2,d3,e1
__device__ float4 g_t1[MAXN];          // e2,tau1,v3,flag
__device__ unsigned char g_key[MAXN];
__device__ int g_cnt[NBKT];
__device__ int g_off[NBKT];
__device__ int g_order[MAXN];

// ---------------------------------------------------------------------------
// Kernel 1: pad positions + zero bucket counters.
// ---------------------------------------------------------------------------
__global__ void pad_kernel(const float* __restrict__ pos, int n) {
    int i = blockIdx.x * blockDim.x + threadIdx.x;
    if (i < NBKT) g_cnt[i] = 0;
    if (i >= n) return;
    float4 p;
    p.x = pos[3 * i + 0];
    p.y = pos[3 * i + 1];
    p.z = pos[3 * i + 2];
    p.w = 0.f;
    g_pos4[i] = p;
}

// ---------------------------------------------------------------------------
// LAPACK fp32 helpers, netlib-expression-faithful (LAPACK >= 3.10).
// FROZEN: arithmetic validated at rel_err 3.4e-7 — do not reorder.
// ---------------------------------------------------------------------------
__device__ __forceinline__ float slapy2f(float x, float y) {
    float xa = fabsf(x), ya = fabsf(y);
    float w = fmaxf(xa, ya), z = fminf(xa, ya);
    if (z == 0.f) return w;
    float t = FDIV(z, w);
    return FMUL(w, sqrtf(FADD(1.f, FMUL(t, t))));
}

__device__ __forceinline__ void slartgf(float f, float g, float& c, float& s,
                                        float& r) {
    if (g == 0.f) {
        c = 1.f; s = 0.f; r = f;
    } else if (f == 0.f) {
        c = 0.f; s = copysignf(1.f, g); r = fabsf(g);
    } else {
        float d = sqrtf(FADD(FMUL(f, f), FMUL(g, g)));
        float p = FDIV(1.f, d);
        c = FMUL(fabsf(f), p);
        s = FMUL(g, copysignf(p, f));
        r = copysignf(d, f);
    }
}

__device__ void slaev2f(float a, float b, float c0, float& rt1, float& rt2,
                        float& cs1, float& sn1) {
    float sm = FADD(a, c0);
    float df = FSUB(a, c0);
    float adf = fabsf(df);
    float tb = FADD(b, b);
    float ab = fabsf(tb);
    float acmx, acmn;
    if (fabsf(a) > fabsf(c0)) { acmx = a; acmn = c0; }
    else { acmx = c0; acmn = a; }
    float rt;
    if (adf > ab) {
        float t = FDIV(ab, adf);
        rt = FMUL(adf, sqrtf(FADD(1.f, FMUL(t, t))));
    } else if (adf < ab) {
        float t = FDIV(adf, ab);
        rt = FMUL(ab, sqrtf(FADD(1.f, FMUL(t, t))));
    } else {
        rt = FMUL(ab, sqrtf(2.f));
    }
    int sgn1;
    if (sm < 0.f) {
        rt1 = FMUL(0.5f, FSUB(sm, rt)); sgn1 = -1;
        rt2 = FSUB(FMUL(FDIV(acmx, rt1), acmn), FMUL(FDIV(b, rt1), b));
    } else if (sm > 0.f) {
        rt1 = FMUL(0.5f, FADD(sm, rt)); sgn1 = 1;
        rt2 = FSUB(FMUL(FDIV(acmx, rt1), acmn), FMUL(FDIV(b, rt1), b));
    } else {
        rt1 = FMUL(0.5f, rt); rt2 = FMUL(-0.5f, rt); sgn1 = 1;
    }
    int sgn2;
    float cs;
    if (df >= 0.f) { cs = FADD(df, rt); sgn2 = 1; }
    else { cs = FSUB(df, rt); sgn2 = -1; }
    float acs = fabsf(cs);
    if (acs > ab) {
        float ct = FDIV(-tb, cs);
        sn1 = FDIV(1.f, sqrtf(FADD(1.f, FMUL(ct, ct))));
        cs1 = FMUL(ct, sn1);
    } else {
        if (ab == 0.f) { cs1 = 1.f; sn1 = 0.f; }
        else {
            float tn = FDIV(-cs, tb);
            cs1 = FDIV(1.f, sqrtf(FADD(1.f, FMUL(tn, tn))));
            sn1 = FMUL(tn, cs1);
        }
    }
    if (sgn1 == sgn2) { float tau = cs1; cs1 = -sn1; sn1 = tau; }
}

// Register-resident index helpers.
__device__ __forceinline__ float sel3(int i, float v1, float v2, float v3) {
    return i == 1 ? v1 : (i == 2 ? v2 : v3);
}
__device__ __forceinline__ float sel2(int i, float v1, float v2) {
    return i == 1 ? v1 : v2;
}
#define SETD(i, x) do { float _x = (x); if ((i) == 1) d1 = _x; \
                        else if ((i) == 2) d2 = _x; else d3 = _x; } while (0)
#define SETE(i, x) do { float _x = (x); if ((i) == 1) e1 = _x; \
                        else e2 = _x; } while (0)

#define ROT12(c, s) do { float _t; \
    _t = z12; z12 = FSUB(FMUL(c, _t), FMUL(s, z11)); z11 = FADD(FMUL(s, _t), FMUL(c, z11)); \
    _t = z22; z22 = FSUB(FMUL(c, _t), FMUL(s, z21)); z21 = FADD(FMUL(s, _t), FMUL(c, z21)); \
    _t = z32; z32 = FSUB(FMUL(c, _t), FMUL(s, z31)); z31 = FADD(FMUL(s, _t), FMUL(c, z31)); \
} while (0)
#define ROT23(c, s) do { float _t; \
    _t = z13; z13 = FSUB(FMUL(c, _t), FMUL(s, z12)); z12 = FADD(FMUL(s, _t), FMUL(c, z12)); \
    _t = z23; z23 = FSUB(FMUL(c, _t), FMUL(s, z22)); z22 = FADD(FMUL(s, _t), FMUL(c, z22)); \
    _t = z33; z33 = FSUB(FMUL(c, _t), FMUL(s, z32)); z32 = FADD(FMUL(s, _t), FMUL(c, z32)); \
} while (0)
#define MROTA(c, s) do { float _t; \
    _t = z11; z11 = FSUB(FMUL(c, _t), FMUL(s, z12)); z12 = FADD(FMUL(s, _t), FMUL(c, z12)); \
    _t = z21; z21 = FSUB(FMUL(c, _t), FMUL(s, z22)); z22 = FADD(FMUL(s, _t), FMUL(c, z22)); \
    _t = z31; z31 = FSUB(FMUL(c, _t), FMUL(s, z32)); z32 = FADD(FMUL(s, _t), FMUL(c, z32)); \
} while (0)
#define MROTB(c, s) do { float _t; \
    _t = z12; z12 = FSUB(FMUL(c, _t), FMUL(s, z13)); z13 = FADD(FMUL(s, _t), FMUL(c, z13)); \
    _t = z22; z22 = FSUB(FMUL(c, _t), FMUL(s, z23)); z23 = FADD(FMUL(s, _t), FMUL(c, z23)); \
    _t = z32; z32 = FSUB(FMUL(c, _t), FMUL(s, z33)); z33 = FADD(FMUL(s, _t), FMUL(c, z33)); \
} while (0)
#define SWAPC12() do { float _t; _t = z11; z11 = z12; z12 = _t; \
    _t = z21; z21 = z22; z22 = _t; _t = z31; z31 = z32; z32 = _t; } while (0)
#define SWAPC13() do { float _t; _t = z11; z11 = z13; z13 = _t; \
    _t = z21; z21 = z23; z23 = _t; _t = z31; z31 = z33; z33 = _t; } while (0)
#define SWAPC23() do { float _t; _t = z12; z12 = z13; z13 = _t; \
    _t = z22; z22 = z23; z23 = _t; _t = z32; z32 = z33; z33 = _t; } while (0)

__device__ __forceinline__ void cov_acc(float4 q, float px, float py, float pz,
                                        float& a00, float& a10, float& a20,
                                        float& a11, float& a21, float& a22) {
    float dx = FSUB(q.x, px);
    float dy = FSUB(q.y, py);
    float dz = FSUB(q.z, pz);
    a00 = FADD(a00, FMUL(dx, dx));
    a10 = FADD(a10, FMUL(dx, dy));
    a20 = FADD(a20, FMUL(dx, dz));
    a11 = FADD(a11, FMUL(dy, dy));
    a21 = FADD(a21, FMUL(dy, dz));
    a22 = FADD(a22, FMUL(dz, dz));
}

// Deflation tests (key heuristic; perf-only if wrong).
__device__ __forceinline__ bool small_e(float e, float da, float db) {
    float t = fabsf(e);
    if (t == 0.f) return true;
    return t <= FMUL(FMUL(sqrtf(fabsf(da)), sqrtf(fabsf(db))), EPSF);
}
__device__ __forceinline__ bool small_e2(float e, float da, float db) {
    float t = FMUL(e, e);
    return t <= FADD(FMUL(FMUL(EPS2F, fabsf(da)), fabsf(db)), SAFMINF);
}

// ---------------------------------------------------------------------------
// Kernel 2: cov + ssytd2 (frozen) -> scratch; path-key -> g_key + g_cnt
// (per-block aggregated atomics).
// ---------------------------------------------------------------------------
__global__ void __launch_bounds__(128, 1)
covtrid_kernel(const int* __restrict__ edge_src,
               const int* __restrict__ num_neighbors,
               float* __restrict__ out, int n, int k) {
    __shared__ int s_cnt[NBKT];
    if (threadIdx.x < NBKT) s_cnt[threadIdx.x] = 0;
    __syncthreads();

    int gi = blockIdx.x * blockDim.x + threadIdx.x;
    int key = -1;
    if (gi < n) {
        if (num_neighbors[gi] <= 1) {
            float* o = out + (long long)gi * 9;
#pragma unroll
            for (int j = 0; j < 9; j++) o[j] = 0.f;
            g_t1[gi] = make_float4(0.f, 0.f, 0.f, 1.f);
            key = 0;
        } else {
            // ============ covariance (frozen arithmetic order) ===========
            float4 pc = g_pos4[gi];
            float px = pc.x, py = pc.y, pz = pc.z;
            float a00 = 0.f, a10 = 0.f, a20 = 0.f;
            float a11 = 0.f, a21 = 0.f, a22 = 0.f;
            const int4* es4 = (const int4*)(edge_src + (long long)gi * k);
#pragma unroll 8
            for (int j = 0; j < k / 4; j++) {
                int4 s4 = es4[j];
                float4 q0 = __ldg(&g_pos4[s4.x]);
                float4 q1 = __ldg(&g_pos4[s4.y]);
                float4 q2 = __ldg(&g_pos4[s4.z]);
                float4 q3 = __ldg(&g_pos4[s4.w]);
                cov_acc(q0, px, py, pz, a00, a10, a20, a11, a21, a22);
                cov_acc(q1, px, py, pz, a00, a10, a20, a11, a21, a22);
                cov_acc(q2, px, py, pz, a00, a10, a20, a11, a21, a22);
                cov_acc(q3, px, py, pz, a00, a10, a20, a11, a21, a22);
            }

            // ============ SSYTD2 (lower), n=3 — FROZEN ============
            float d1, d2, d3, e1, e2;
            float tau1 = 0.f, v3 = 0.f;
            {
                float alpha = a10;
                float x = a20;
                if (x == 0.f) {
                    tau1 = 0.f;
                    e1 = alpha;
                } else {
                    float beta = -copysignf(slapy2f(alpha, x), alpha);
                    tau1 = FDIV(FSUB(beta, alpha), beta);
                    float rcp = FDIV(1.f, FSUB(alpha, beta));
                    v3 = FMUL(x, rcp);
                    e1 = beta;
                    float w1 = FADD(FMUL(tau1, a11), FMUL(tau1, FMUL(a21, v3)));
                    float w2 = FADD(FMUL(tau1, a21), FMUL(FMUL(tau1, v3), a22));
                    float dot = FADD(w1, FMUL(w2, v3));
                    float al2 = -FMUL(FMUL(0.5f, tau1), dot);
                    w1 = FADD(w1, al2);
                    w2 = FADD(w2, FMUL(al2, v3));
                    a11 = FADD(FADD(a11, -w1), -w1);
                    a21 = FADD(FADD(a21, FMUL(v3, -w1)), -w2);
                    a22 = FADD(FADD(a22, FMUL(v3, -w2)), FMUL(w2, -v3));
                }
                e2 = a21;
                d1 = a00; d2 = a11; d3 = a22;
            }

            g_t0[gi] = make_float4(d1, d2, d3, e1);
            g_t1[gi] = make_float4(e2, tau1, v3, 0.f);

            // ============ path key (scheduling only) ============
            int m = 3;
            if (small_e(e1, d1, d2)) m = 1;
            else if (small_e(e2, d2, d3)) m = 2;

            int ql, cse;
            if (m == 1) {
                if (small_e(e2, d2, d3)) {
                    ql = 0; cse = 3;
                } else {
                    ql = (fabsf(d3) < fabsf(d2)) ? 0 : 1;
                    cse = small_e2(e2, ql ? d2 : d3, ql ? d3 : d2) ? 0 : 1;
                }
            } else if (m == 2) {
                ql = (fabsf(d2) < fabsf(d1)) ? 0 : 1;
                cse = small_e2(e1, ql ? d1 : d2, ql ? d2 : d1) ? 0 : 1;
            } else {
                ql = (fabsf(d3) < fabsf(d1)) ? 0 : 1;
                if (ql) {
                    if (small_e2(e1, d1, d2)) cse = 0;
                    else if (small_e2(e2, d2, d3)) cse = 1;
                    else cse = 2;
                } else {
                    if (small_e2(e2, d3, d2)) cse = 0;
                    else if (small_e2(e1, d2, d1)) cse = 1;
                    else cse = 2;
                }
            }
            key = 1 + ((m - 1) << 3) + (ql << 2) + cse;   // 1..27 < NBKT
        }
        g_key[gi] = (unsigned char)key;
        atomicAdd(&s_cnt[key], 1);
    }
    __syncthreads();
    if (threadIdx.x < NBKT && s_cnt[threadIdx.x] > 0)
        atomicAdd(&g_cnt[threadIdx.x], s_cnt[threadIdx.x]);
}

// ---------------------------------------------------------------------------
// Kernel 3: exclusive scan of 32 bucket counts (1 thread).
// ---------------------------------------------------------------------------
__global__ void scan_kernel() {
    if (threadIdx.x == 0 && blockIdx.x == 0) {
        int run = 0;
        for (int b = 0; b < NBKT; b++) {
            g_off[b] = run;
            run += g_cnt[b];
        }
    }
}

// ---------------------------------------------------------------------------
// Kernel 4: two-level scatter — shared-memory ranking per block, ONE global
// atomicAdd per (block, bucket). Kills the 32-address contention.
// ---------------------------------------------------------------------------
__global__ void scatter_kernel(int n) {
    __shared__ int s_cnt[NBKT];
    __shared__ int s_base[NBKT];
    int t = threadIdx.x;
    if (t < NBKT) s_cnt[t] = 0;
    __syncthreads();

    int i = blockIdx.x * blockDim.x + t;
    int key = 0, rank = 0;
    if (i < n) {
        key = g_key[i];
        rank = atomicAdd(&s_cnt[key], 1);
    }
    __syncthreads();
    if (t < NBKT) {
        int c = s_cnt[t];
        s_base[t] = (c > 0) ? atomicAdd(&g_off[t], c) : 0;
    }
    __syncthreads();
    if (i < n) g_order[s_base[key] + rank] = i;
}

// ---------------------------------------------------------------------------
// Kernel 5: ssteqr('I') + sormtr per node, bucket-sorted (path-homogeneous
// warps). Solver arithmetic FROZEN (identical to validated R9 code).
// ---------------------------------------------------------------------------
__global__ void __launch_bounds__(128, 1)
eig_kernel(float* __restrict__ out, int n) {
    int tid = blockIdx.x * blockDim.x + threadIdx.x;
    if (tid >= n) return;
    int gi = g_order[tid];

    float4 t0 = g_t0[gi];
    float4 t1 = g_t1[gi];
    if (t1.w != 0.f) return;    // zero-neighbor node: out already written

    float d1 = t0.x, d2 = t0.y, d3 = t0.z, e1 = t0.w;
    float e2 = t1.x, tau1 = t1.y, v3 = t1.z;

    const float eps = EPSF;
    const float eps2 = FMUL(eps, eps);
    const float safmin = SAFMINF;
    const int nmaxit = 90;
    int jtot = 0;

    float z11 = 1.f, z21 = 0.f, z31 = 0.f;
    float z12 = 0.f, z22 = 1.f, z32 = 0.f;
    float z13 = 0.f, z23 = 0.f, z33 = 1.f;

    int l1 = 1;
    while (l1 <= 3) {
        if (l1 > 1) SETE(l1 - 1, 0.f);
        int m = 3;
        for (int mm = l1; mm <= 2; mm++) {
            float tst = fabsf(sel2(mm, e1, e2));
            if (tst == 0.f) { m = mm; break; }
            if (tst <= FMUL(FMUL(sqrtf(fabsf(sel3(mm, d1, d2, d3))),
                                 sqrtf(fabsf(sel3(mm + 1, d1, d2, d3)))),
                            eps)) {
                SETE(mm, 0.f);
                m = mm; break;
            }
        }
        int l = l1, lsv = l, lend = m, lendsv = lend;
        l1 = m + 1;
        if (lend == l) continue;

        float anorm = 0.f;
        for (int i = l; i <= lend; i++)
            anorm = fmaxf(anorm, fabsf(sel3(i, d1, d2, d3)));
        for (int i = l; i <= lend - 1; i++)
            anorm = fmaxf(anorm, fabsf(sel2(i, e1, e2)));
        if (anorm == 0.f) continue;

        if (fabsf(sel3(lend, d1, d2, d3)) < fabsf(sel3(l, d1, d2, d3))) {
            lend = lsv; l = lendsv;
        }

        bool ql = (lend > l);
        int lv = ql ? l : 4 - l;
        int lendv = ql ? lend : 4 - lend;

        while (1) {
            int m2 = lendv;
            if (lv != lendv) {
                for (int mm = lv; mm <= lendv - 1; mm++) {
                    float emm = sel2(ql ? mm : 3 - mm, e1, e2);
                    float tst = FMUL(emm, emm);
                    float dmm = sel3(ql ? mm : 4 - mm, d1, d2, d3);
                    float dmm1 = sel3(ql ? mm + 1 : 3 - mm, d1, d2, d3);
                    if (tst <= FADD(FMUL(FMUL(eps2, fabsf(dmm)), fabsf(dmm1)),
                                    safmin)) {
                        m2 = mm; break;
                    }
                }
            }
            if (m2 < lendv) SETE(ql ? m2 : 3 - m2, 0.f);
            float p = sel3(ql ? lv : 4 - lv, d1, d2, d3);
            if (m2 == lv) {
                lv = lv + 1;
                if (lv <= lendv) continue;
                break;
            }
            if (m2 == lv + 1) {
                float rt1, rt2, c, s;
                float bb = sel2(ql ? lv : 3 - lv, e1, e2);
                float aa, cc;
                if (ql) {
                    aa = sel3(lv, d1, d2, d3);
                    cc = sel3(lv + 1, d1, d2, d3);
                } else {
                    aa = sel3(3 - lv, d1, d2, d3);
                    cc = sel3(4 - lv, d1, d2, d3);
                }
                slaev2f(aa, bb, cc, rt1, rt2, c, s);
                if ((ql && lv == 1) || (!ql && lv == 2)) { ROT12(c, s); }
                else { ROT23(c, s); }
                if (ql) {
                    SETD(lv, rt1); SETD(lv + 1, rt2); SETE(lv, 0.f);
                } else {
                    SETD(3 - lv, rt1); SETD(4 - lv, rt2); SETE(3 - lv, 0.f);
                }
                lv = lv + 2;
                if (lv <= lendv) continue;
                break;
            }
            if (jtot == nmaxit) break;
            jtot++;
            float vd1 = ql ? d1 : d3, vd3 = ql ? d3 : d1;
            float ve1 = ql ? e1 : e2, ve2 = ql ? e2 : e1;
            float g = FDIV(FSUB(d2, p), FMUL(2.f, ve1));
            float r = slapy2f(g, 1.f);
            g = FADD(FSUB(vd3, p), FDIV(ve1, FADD(g, copysignf(r, g))));
            float s = 1.f, c = 1.f;
            p = 0.f;
            float wc1, wc2, ws1, ws2;
            {   // virtual i = 2
                float f = FMUL(s, ve2);
                float b = FMUL(c, ve2);
                slartgf(g, f, c, s, r);
                g = FSUB(vd3, p);
                r = FADD(FMUL(FSUB(d2, g), s), FMUL(FMUL(2.f, c), b));
                p = FMUL(s, r);
                vd3 = FADD(g, p);
                g = FSUB(FMUL(c, r), b);
                wc2 = c; ws2 = -s;
            }
            {   // virtual i = 1
                float f = FMUL(s, ve1);
                float b = FMUL(c, ve1);
                slartgf(g, f, c, s, r);
                ve2 = r;
                g = FSUB(d2, p);
                r = FADD(FMUL(FSUB(vd1, g), s), FMUL(FMUL(2.f, c), b));
                p = FMUL(s, r);
                d2 = FADD(g, p);
                g = FSUB(FMUL(c, r), b);
                wc1 = c; ws1 = -s;
            }
            if (wc2 != 1.f || ws2 != 0.f) {
                if (ql) { ROT23(wc2, ws2); } else { MROTA(wc2, ws2); }
            }
            if (wc1 != 1.f || ws1 != 0.f) {
                if (ql) { ROT12(wc1, ws1); } else { MROTB(wc1, ws1); }
            }
            vd1 = FSUB(vd1, p);
            ve1 = g;
            if (ql) { d1 = vd1; d3 = vd3; e1 = ve1; e2 = ve2; }
            else    { d3 = vd1; d1 = vd3; e2 = ve1; e1 = ve2; }
        }
    }

    // selection sort (ascending, column swaps)
    {
        int kk = 1; float p = d1;
        if (d2 < p) { kk = 2; p = d2; }
        if (d3 < p) { kk = 3; p = d3; }
        if (kk == 2) { d2 = d1; d1 = p; SWAPC12(); }
        else if (kk == 3) { d3 = d1; d1 = p; SWAPC13(); }
    }
    {
        if (d3 < d2) { float p = d2; d2 = d3; d3 = p; SWAPC23(); }
    }

    // SORMTR: Z := H(1)*Z
    if (tau1 != 0.f) {
        float w, t;
        w = FADD(z21, FMUL(z31, v3)); t = FMUL(-tau1, w);
        z21 = FADD(z21, t); z31 = FADD(z31, FMUL(v3, t));
        w = FADD(z22, FMUL(z32, v3)); t = FMUL(-tau1, w);
        z22 = FADD(z22, t); z32 = FADD(z32, FMUL(v3, t));
        w = FADD(z23, FMUL(z33, v3)); t = FMUL(-tau1, w);
        z23 = FADD(z23, t); z33 = FADD(z33, FMUL(v3, t));
    }

    float* o = out + (long long)gi * 9;
    o[0] = z11; o[1] = z21; o[2] = z31;
    o[3] = z12; o[4] = z22; o[5] = z32;
    o[6] = z13; o[7] = z23; o[8] = z33;
}

// ---------------------------------------------------------------------------
// Launch
// ---------------------------------------------------------------------------
extern "C" void kernel_launch(void* const* d_in, const int* in_sizes, int n_in,
                              void* d_out, int out_size) {
    const float* pos = (const float*)d_in[0];
    const int* edge_src = (const int*)d_in[1];
    // d_in[2] = edge_dst: unused (edge_dst == repeat(arange(n), k))
    const int* num_neighbors = (const int*)d_in[3];

    int n = in_sizes[3];
    int k = in_sizes[1] / n;

    pad_kernel<<<(n + 255) / 256, 256>>>(pos, n);
    covtrid_kernel<<<(n + 127) / 128, 128>>>(edge_src, num_neighbors,
                                             (float*)d_out, n, k);
    scan_kernel<<<1, 32>>>();
    scatter_kernel<<<(n + 511) / 512, 512>>>(n);
    eig_kernel<<<(n + 127) / 128, 128>>>((float*)d_out, n);
}

// round 12
// speedup vs baseline: 2.1556x; 1.2667x over previous
#include <cuda_runtime.h>
#include <math.h>

#define MAXN 32768
#define NBKT 32
#define BLK 256

#define FADD __fadd_rn
#define FSUB __fsub_rn
#define FMUL __fmul_rn
#define FDIV __fdiv_rn

#define EPSF   5.9604644775390625e-08f     // 2^-24
#define EPS2F  (EPSF * EPSF)
#define SAFMINF 1.1754943508222875e-38f    // 2^-126

// 16B-aligned padded positions: one LDG.128 per neighbor gather.
__device__ float4 g_pos4[MAXN];

// ---------------------------------------------------------------------------
// Kernel A: pad pos[3*i..3*i+2] -> g_pos4[i].
// ---------------------------------------------------------------------------
__global__ void pad_kernel(const float* __restrict__ pos, int n) {
    int i = blockIdx.x * blockDim.x + threadIdx.x;
    if (i >= n) return;
    float4 p;
    p.x = pos[3 * i + 0];
    p.y = pos[3 * i + 1];
    p.z = pos[3 * i + 2];
    p.w = 0.f;
    g_pos4[i] = p;
}

// ---------------------------------------------------------------------------
// LAPACK fp32 helpers, netlib-expression-faithful (LAPACK >= 3.10).
// FROZEN: arithmetic validated at rel_err 3.4e-7 — do not reorder.
// ---------------------------------------------------------------------------
__device__ __forceinline__ float slapy2f(float x, float y) {
    float xa = fabsf(x), ya = fabsf(y);
    float w = fmaxf(xa, ya), z = fminf(xa, ya);
    if (z == 0.f) return w;
    float t = FDIV(z, w);
    return FMUL(w, sqrtf(FADD(1.f, FMUL(t, t))));
}

__device__ __forceinline__ void slartgf(float f, float g, float& c, float& s,
                                        float& r) {
    if (g == 0.f) {
        c = 1.f; s = 0.f; r = f;
    } else if (f == 0.f) {
        c = 0.f; s = copysignf(1.f, g); r = fabsf(g);
    } else {
        float d = sqrtf(FADD(FMUL(f, f), FMUL(g, g)));
        float p = FDIV(1.f, d);
        c = FMUL(fabsf(f), p);
        s = FMUL(g, copysignf(p, f));
        r = copysignf(d, f);
    }
}

__device__ void slaev2f(float a, float b, float c0, float& rt1, float& rt2,
                        float& cs1, float& sn1) {
    float sm = FADD(a, c0);
    float df = FSUB(a, c0);
    float adf = fabsf(df);
    float tb = FADD(b, b);
    float ab = fabsf(tb);
    float acmx, acmn;
    if (fabsf(a) > fabsf(c0)) { acmx = a; acmn = c0; }
    else { acmx = c0; acmn = a; }
    float rt;
    if (adf > ab) {
        float t = FDIV(ab, adf);
        rt = FMUL(adf, sqrtf(FADD(1.f, FMUL(t, t))));
    } else if (adf < ab) {
        float t = FDIV(adf, ab);
        rt = FMUL(ab, sqrtf(FADD(1.f, FMUL(t, t))));
    } else {
        rt = FMUL(ab, sqrtf(2.f));
    }
    int sgn1;
    if (sm < 0.f) {
        rt1 = FMUL(0.5f, FSUB(sm, rt)); sgn1 = -1;
        rt2 = FSUB(FMUL(FDIV(acmx, rt1), acmn), FMUL(FDIV(b, rt1), b));
    } else if (sm > 0.f) {
        rt1 = FMUL(0.5f, FADD(sm, rt)); sgn1 = 1;
        rt2 = FSUB(FMUL(FDIV(acmx, rt1), acmn), FMUL(FDIV(b, rt1), b));
    } else {
        rt1 = FMUL(0.5f, rt); rt2 = FMUL(-0.5f, rt); sgn1 = 1;
    }
    int sgn2;
    float cs;
    if (df >= 0.f) { cs = FADD(df, rt); sgn2 = 1; }
    else { cs = FSUB(df, rt); sgn2 = -1; }
    float acs = fabsf(cs);
    if (acs > ab) {
        float ct = FDIV(-tb, cs);
        sn1 = FDIV(1.f, sqrtf(FADD(1.f, FMUL(ct, ct))));
        cs1 = FMUL(ct, sn1);
    } else {
        if (ab == 0.f) { cs1 = 1.f; sn1 = 0.f; }
        else {
            float tn = FDIV(-cs, tb);
            cs1 = FDIV(1.f, sqrtf(FADD(1.f, FMUL(tn, tn))));
            sn1 = FMUL(tn, cs1);
        }
    }
    if (sgn1 == sgn2) { float tau = cs1; cs1 = -sn1; sn1 = tau; }
}

// Register-resident index helpers.
__device__ __forceinline__ float sel3(int i, float v1, float v2, float v3) {
    return i == 1 ? v1 : (i == 2 ? v2 : v3);
}
__device__ __forceinline__ float sel2(int i, float v1, float v2) {
    return i == 1 ? v1 : v2;
}
#define SETD(i, x) do { float _x = (x); if ((i) == 1) d1 = _x; \
                        else if ((i) == 2) d2 = _x; else d3 = _x; } while (0)
#define SETE(i, x) do { float _x = (x); if ((i) == 1) e1 = _x; \
                        else e2 = _x; } while (0)

#define ROT12(c, s) do { float _t; \
    _t = z12; z12 = FSUB(FMUL(c, _t), FMUL(s, z11)); z11 = FADD(FMUL(s, _t), FMUL(c, z11)); \
    _t = z22; z22 = FSUB(FMUL(c, _t), FMUL(s, z21)); z21 = FADD(FMUL(s, _t), FMUL(c, z21)); \
    _t = z32; z32 = FSUB(FMUL(c, _t), FMUL(s, z31)); z31 = FADD(FMUL(s, _t), FMUL(c, z31)); \
} while (0)
#define ROT23(c, s) do { float _t; \
    _t = z13; z13 = FSUB(FMUL(c, _t), FMUL(s, z12)); z12 = FADD(FMUL(s, _t), FMUL(c, z12)); \
    _t = z23; z23 = FSUB(FMUL(c, _t), FMUL(s, z22)); z22 = FADD(FMUL(s, _t), FMUL(c, z22)); \
    _t = z33; z33 = FSUB(FMUL(c, _t), FMUL(s, z32)); z32 = FADD(FMUL(s, _t), FMUL(c, z32)); \
} while (0)
#define MROTA(c, s) do { float _t; \
    _t = z11; z11 = FSUB(FMUL(c, _t), FMUL(s, z12)); z12 = FADD(FMUL(s, _t), FMUL(c, z12)); \
    _t = z21; z21 = FSUB(FMUL(c, _t), FMUL(s, z22)); z22 = FADD(FMUL(s, _t), FMUL(c, z22)); \
    _t = z31; z31 = FSUB(FMUL(c, _t), FMUL(s, z32)); z32 = FADD(FMUL(s, _t), FMUL(c, z32)); \
} while (0)
#define MROTB(c, s) do { float _t; \
    _t = z12; z12 = FSUB(FMUL(c, _t), FMUL(s, z13)); z13 = FADD(FMUL(s, _t), FMUL(c, z13)); \
    _t = z22; z22 = FSUB(FMUL(c, _t), FMUL(s, z23)); z23 = FADD(FMUL(s, _t), FMUL(c, z23)); \
    _t = z32; z32 = FSUB(FMUL(c, _t), FMUL(s, z33)); z33 = FADD(FMUL(s, _t), FMUL(c, z33)); \
} while (0)
#define SWAPC12() do { float _t; _t = z11; z11 = z12; z12 = _t; \
    _t = z21; z21 = z22; z22 = _t; _t = z31; z31 = z32; z32 = _t; } while (0)
#define SWAPC13() do { float _t; _t = z11; z11 = z13; z13 = _t; \
    _t = z21; z21 = z23; z23 = _t; _t = z31; z31 = z33; z33 = _t; } while (0)
#define SWAPC23() do { float _t; _t = z12; z12 = z13; z13 = _t; \
    _t = z22; z22 = z23; z23 = _t; _t = z32; z32 = z33; z33 = _t; } while (0)

__device__ __forceinline__ void cov_acc(float4 q, float px, float py, float pz,
                                        float& a00, float& a10, float& a20,
                                        float& a11, float& a21, float& a22) {
    float dx = FSUB(q.x, px);
    float dy = FSUB(q.y, py);
    float dz = FSUB(q.z, pz);
    a00 = FADD(a00, FMUL(dx, dx));
    a10 = FADD(a10, FMUL(dx, dy));
    a20 = FADD(a20, FMUL(dx, dz));
    a11 = FADD(a11, FMUL(dy, dy));
    a21 = FADD(a21, FMUL(dy, dz));
    a22 = FADD(a22, FMUL(dz, dz));
}

// Deflation tests (key heuristic; perf-only if wrong).
__device__ __forceinline__ bool small_e(float e, float da, float db) {
    float t = fabsf(e);
    if (t == 0.f) return true;
    return t <= FMUL(FMUL(sqrtf(fabsf(da)), sqrtf(fabsf(db))), EPSF);
}
__device__ __forceinline__ bool small_e2(float e, float da, float db) {
    float t = FMUL(e, e);
    return t <= FADD(FMUL(FMUL(EPS2F, fabsf(da)), fabsf(db)), SAFMINF);
}

// ---------------------------------------------------------------------------
// Fused kernel: cov + ssytd2 -> block-local bucket sort (shared mem) ->
// ssteqr('I') + sormtr on path-homogeneous warps. Solver bits FROZEN.
// ---------------------------------------------------------------------------
__global__ void __launch_bounds__(BLK, 1)
fused_kernel(const int* __restrict__ edge_src,
             const int* __restrict__ num_neighbors,
             float* __restrict__ out, int n, int k) {
    __shared__ float s_rec[7][BLK];   // d1,d2,d3,e1,e2,tau1,v3 (sorted order)
    __shared__ int s_gid[BLK];
    __shared__ int s_cnt[NBKT];
    __shared__ int s_off[NBKT];

    int t = threadIdx.x;
    if (t < NBKT) s_cnt[t] = 0;
    __syncthreads();

    int gi = blockIdx.x * BLK + t;
    int key = 0, rank = 0;
    bool active = false;
    float d1, d2, d3, e1, e2, tau1 = 0.f, v3 = 0.f;

    if (gi < n) {
        if (num_neighbors[gi] <= 1) {
            float* o = out + (long long)gi * 9;
#pragma unroll
            for (int j = 0; j < 9; j++) o[j] = 0.f;
        } else {
            active = true;
            // ============ covariance (frozen arithmetic order) ===========
            float4 pc = g_pos4[gi];
            float px = pc.x, py = pc.y, pz = pc.z;
            float a00 = 0.f, a10 = 0.f, a20 = 0.f;
            float a11 = 0.f, a21 = 0.f, a22 = 0.f;
            const int4* es4 = (const int4*)(edge_src + (long long)gi * k);
#pragma unroll 8
            for (int j = 0; j < k / 4; j++) {
                int4 s4 = es4[j];
                float4 q0 = __ldg(&g_pos4[s4.x]);
                float4 q1 = __ldg(&g_pos4[s4.y]);
                float4 q2 = __ldg(&g_pos4[s4.z]);
                float4 q3 = __ldg(&g_pos4[s4.w]);
                cov_acc(q0, px, py, pz, a00, a10, a20, a11, a21, a22);
                cov_acc(q1, px, py, pz, a00, a10, a20, a11, a21, a22);
                cov_acc(q2, px, py, pz, a00, a10, a20, a11, a21, a22);
                cov_acc(q3, px, py, pz, a00, a10, a20, a11, a21, a22);
            }

            // ============ SSYTD2 (lower), n=3 — FROZEN ============
            {
                float alpha = a10;
                float x = a20;
                if (x == 0.f) {
                    tau1 = 0.f;
                    e1 = alpha;
                } else {
                    float beta = -copysignf(slapy2f(alpha, x), alpha);
                    tau1 = FDIV(FSUB(beta, alpha), beta);
                    float rcp = FDIV(1.f, FSUB(alpha, beta));
                    v3 = FMUL(x, rcp);
                    e1 = beta;
                    float w1 = FADD(FMUL(tau1, a11), FMUL(tau1, FMUL(a21, v3)));
                    float w2 = FADD(FMUL(tau1, a21), FMUL(FMUL(tau1, v3), a22));
                    float dot = FADD(w1, FMUL(w2, v3));
                    float al2 = -FMUL(FMUL(0.5f, tau1), dot);
                    w1 = FADD(w1, al2);
                    w2 = FADD(w2, FMUL(al2, v3));
                    a11 = FADD(FADD(a11, -w1), -w1);
                    a21 = FADD(FADD(a21, FMUL(v3, -w1)), -w2);
                    a22 = FADD(FADD(a22, FMUL(v3, -w2)), FMUL(w2, -v3));
                }
                e2 = a21;
                d1 = a00; d2 = a11; d3 = a22;
            }

            // ============ path key (scheduling only) ============
            int m = 3;
            if (small_e(e1, d1, d2)) m = 1;
            else if (small_e(e2, d2, d3)) m = 2;

            int ql, cse;
            if (m == 1) {
                if (small_e(e2, d2, d3)) {
                    ql = 0; cse = 3;
                } else {
                    ql = (fabsf(d3) < fabsf(d2)) ? 0 : 1;
                    cse = small_e2(e2, ql ? d2 : d3, ql ? d3 : d2) ? 0 : 1;
                }
            } else if (m == 2) {
                ql = (fabsf(d2) < fabsf(d1)) ? 0 : 1;
                cse = small_e2(e1, ql ? d1 : d2, ql ? d2 : d1) ? 0 : 1;
            } else {
                ql = (fabsf(d3) < fabsf(d1)) ? 0 : 1;
                if (ql) {
                    if (small_e2(e1, d1, d2)) cse = 0;
                    else if (small_e2(e2, d2, d3)) cse = 1;
                    else cse = 2;
                } else {
                    if (small_e2(e2, d3, d2)) cse = 0;
                    else if (small_e2(e1, d2, d1)) cse = 1;
                    else cse = 2;
                }
            }
            key = ((m - 1) << 3) + (ql << 2) + cse;   // 0..26 < NBKT
            rank = atomicAdd(&s_cnt[key], 1);
        }
    }
    __syncthreads();

    if (t == 0) {
        int run = 0;
#pragma unroll
        for (int b = 0; b < NBKT; b++) {
            s_off[b] = run;
            run += s_cnt[b];
        }
    }
    __syncthreads();

    if (active) {
        int pos = s_off[key] + rank;
        s_rec[0][pos] = d1;
        s_rec[1][pos] = d2;
        s_rec[2][pos] = d3;
        s_rec[3][pos] = e1;
        s_rec[4][pos] = e2;
        s_rec[5][pos] = tau1;
        s_rec[6][pos] = v3;
        s_gid[pos] = gi;
    }
    int total = s_off[NBKT - 1] + s_cnt[NBKT - 1];
    __syncthreads();

    if (t >= total) return;

    // Load t-th sorted record (bit-identical values; scheduling only).
    d1 = s_rec[0][t];
    d2 = s_rec[1][t];
    d3 = s_rec[2][t];
    e1 = s_rec[3][t];
    e2 = s_rec[4][t];
    tau1 = s_rec[5][t];
    v3 = s_rec[6][t];
    int ogi = s_gid[t];

    // ================= SSTEQR('I'), n=3 — FROZEN (R9 unified) =============
    const float eps = EPSF;
    const float eps2 = FMUL(eps, eps);
    const float safmin = SAFMINF;
    const int nmaxit = 90;
    int jtot = 0;

    float z11 = 1.f, z21 = 0.f, z31 = 0.f;
    float z12 = 0.f, z22 = 1.f, z32 = 0.f;
    float z13 = 0.f, z23 = 0.f, z33 = 1.f;

    int l1 = 1;
    while (l1 <= 3) {
        if (l1 > 1) SETE(l1 - 1, 0.f);
        int m = 3;
        for (int mm = l1; mm <= 2; mm++) {
            float tst = fabsf(sel2(mm, e1, e2));
            if (tst == 0.f) { m = mm; break; }
            if (tst <= FMUL(FMUL(sqrtf(fabsf(sel3(mm, d1, d2, d3))),
                                 sqrtf(fabsf(sel3(mm + 1, d1, d2, d3)))),
                            eps)) {
                SETE(mm, 0.f);
                m = mm; break;
            }
        }
        int l = l1, lsv = l, lend = m, lendsv = lend;
        l1 = m + 1;
        if (lend == l) continue;

        float anorm = 0.f;
        for (int i = l; i <= lend; i++)
            anorm = fmaxf(anorm, fabsf(sel3(i, d1, d2, d3)));
        for (int i = l; i <= lend - 1; i++)
            anorm = fmaxf(anorm, fabsf(sel2(i, e1, e2)));
        if (anorm == 0.f) continue;

        if (fabsf(sel3(lend, d1, d2, d3)) < fabsf(sel3(l, d1, d2, d3))) {
            lend = lsv; l = lendsv;
        }

        bool ql = (lend > l);
        int lv = ql ? l : 4 - l;
        int lendv = ql ? lend : 4 - lend;

        while (1) {
            int m2 = lendv;
            if (lv != lendv) {
                for (int mm = lv; mm <= lendv - 1; mm++) {
                    float emm = sel2(ql ? mm : 3 - mm, e1, e2);
                    float tst = FMUL(emm, emm);
                    float dmm = sel3(ql ? mm : 4 - mm, d1, d2, d3);
                    float dmm1 = sel3(ql ? mm + 1 : 3 - mm, d1, d2, d3);
                    if (tst <= FADD(FMUL(FMUL(eps2, fabsf(dmm)), fabsf(dmm1)),
                                    safmin)) {
                        m2 = mm; break;
                    }
                }
            }
            if (m2 < lendv) SETE(ql ? m2 : 3 - m2, 0.f);
            float p = sel3(ql ? lv : 4 - lv, d1, d2, d3);
            if (m2 == lv) {
                lv = lv + 1;
                if (lv <= lendv) continue;
                break;
            }
            if (m2 == lv + 1) {
                float rt1, rt2, c, s;
                float bb = sel2(ql ? lv : 3 - lv, e1, e2);
                float aa, cc;
                if (ql) {
                    aa = sel3(lv, d1, d2, d3);
                    cc = sel3(lv + 1, d1, d2, d3);
                } else {
                    aa = sel3(3 - lv, d1, d2, d3);
                    cc = sel3(4 - lv, d1, d2, d3);
                }
                slaev2f(aa, bb, cc, rt1, rt2, c, s);
                if ((ql && lv == 1) || (!ql && lv == 2)) { ROT12(c, s); }
                else { ROT23(c, s); }
                if (ql) {
                    SETD(lv, rt1); SETD(lv + 1, rt2); SETE(lv, 0.f);
                } else {
                    SETD(3 - lv, rt1); SETD(4 - lv, rt2); SETE(3 - lv, 0.f);
                }
                lv = lv + 2;
                if (lv <= lendv) continue;
                break;
            }
            if (jtot == nmaxit) break;
            jtot++;
            float vd1 = ql ? d1 : d3, vd3 = ql ? d3 : d1;
            float ve1 = ql ? e1 : e2, ve2 = ql ? e2 : e1;
            float g = FDIV(FSUB(d2, p), FMUL(2.f, ve1));
            float r = slapy2f(g, 1.f);
            g = FADD(FSUB(vd3, p), FDIV(ve1, FADD(g, copysignf(r, g))));
            float s = 1.f, c = 1.f;
            p = 0.f;
            float wc1, wc2, ws1, ws2;
            {   // virtual i = 2
                float f = FMUL(s, ve2);
                float b = FMUL(c, ve2);
                slartgf(g, f, c, s, r);
                g = FSUB(vd3, p);
                r = FADD(FMUL(FSUB(d2, g), s), FMUL(FMUL(2.f, c), b));
                p = FMUL(s, r);
                vd3 = FADD(g, p);
                g = FSUB(FMUL(c, r), b);
                wc2 = c; ws2 = -s;
            }
            {   // virtual i = 1
                float f = FMUL(s, ve1);
                float b = FMUL(c, ve1);
                slartgf(g, f, c, s, r);
                ve2 = r;
                g = FSUB(d2, p);
                r = FADD(FMUL(FSUB(vd1, g), s), FMUL(FMUL(2.f, c), b));
                p = FMUL(s, r);
                d2 = FADD(g, p);
                g = FSUB(FMUL(c, r), b);
                wc1 = c; ws1 = -s;
            }
            if (wc2 != 1.f || ws2 != 0.f) {
                if (ql) { ROT23(wc2, ws2); } else { MROTA(wc2, ws2); }
            }
            if (wc1 != 1.f || ws1 != 0.f) {
                if (ql) { ROT12(wc1, ws1); } else { MROTB(wc1, ws1); }
            }
            vd1 = FSUB(vd1, p);
            ve1 = g;
            if (ql) { d1 = vd1; d3 = vd3; e1 = ve1; e2 = ve2; }
            else    { d3 = vd1; d1 = vd3; e2 = ve1; e1 = ve2; }
        }
    }

    // selection sort (ascending, column swaps)
    {
        int kk = 1; float p = d1;
        if (d2 < p) { kk = 2; p = d2; }
        if (d3 < p) { kk = 3; p = d3; }
        if (kk == 2) { d2 = d1; d1 = p; SWAPC12(); }
        else if (kk == 3) { d3 = d1; d1 = p; SWAPC13(); }
    }
    {
        if (d3 < d2) { float p = d2; d2 = d3; d3 = p; SWAPC23(); }
    }

    // SORMTR: Z := H(1)*Z
    if (tau1 != 0.f) {
        float w, tt;
        w = FADD(z21, FMUL(z31, v3)); tt = FMUL(-tau1, w);
        z21 = FADD(z21, tt); z31 = FADD(z31, FMUL(v3, tt));
        w = FADD(z22, FMUL(z32, v3)); tt = FMUL(-tau1, w);
        z22 = FADD(z22, tt); z32 = FADD(z32, FMUL(v3, tt));
        w = FADD(z23, FMUL(z33, v3)); tt = FMUL(-tau1, w);
        z23 = FADD(z23, tt); z33 = FADD(z33, FMUL(v3, tt));
    }

    float* o = out + (long long)ogi * 9;
    o[0] = z11; o[1] = z21; o[2] = z31;
    o[3] = z12; o[4] = z22; o[5] = z32;
    o[6] = z13; o[7] = z23; o[8] = z33;
}

// ---------------------------------------------------------------------------
// Launch
// ---------------------------------------------------------------------------
extern "C" void kernel_launch(void* const* d_in, const int* in_sizes, int n_in,
                              void* d_out, int out_size) {
    const float* pos = (const float*)d_in[0];
    const int* edge_src = (const int*)d_in[1];
    // d_in[2] = edge_dst: unused (edge_dst == repeat(arange(n), k))
    const int* num_neighbors = (const int*)d_in[3];

    int n = in_sizes[3];
    int k = in_sizes[1] / n;

    pad_kernel<<<(n + 255) / 256, 256>>>(pos, n);
    fused_kernel<<<(n + BLK - 1) / BLK, BLK>>>(edge_src, num_neighbors,
                                               (float*)d_out, n, k);
}

// round 13
// speedup vs baseline: 2.1616x; 1.0028x over previous
#include <cuda_runtime.h>
#include <math.h>

#define MAXN 32768
#define NBKT 32
#define BLK 224   // 7 warps: ceil(32768/148) rounded to warp => 1 block per SM

#define FADD __fadd_rn
#define FSUB __fsub_rn
#define FMUL __fmul_rn
#define FDIV __fdiv_rn

#define EPSF   5.9604644775390625e-08f     // 2^-24
#define EPS2F  (EPSF * EPSF)
#define SAFMINF 1.1754943508222875e-38f    // 2^-126

// 16B-aligned padded positions: one LDG.128 per neighbor gather.
__device__ float4 g_pos4[MAXN];

// ---------------------------------------------------------------------------
// Kernel A: pad pos[3*i..3*i+2] -> g_pos4[i].
// ---------------------------------------------------------------------------
__global__ void pad_kernel(const float* __restrict__ pos, int n) {
    int i = blockIdx.x * blockDim.x + threadIdx.x;
    if (i >= n) return;
    float4 p;
    p.x = pos[3 * i + 0];
    p.y = pos[3 * i + 1];
    p.z = pos[3 * i + 2];
    p.w = 0.f;
    g_pos4[i] = p;
}

// ---------------------------------------------------------------------------
// LAPACK fp32 helpers, netlib-expression-faithful (LAPACK >= 3.10).
// FROZEN: arithmetic validated at rel_err 3.4e-7 — do not reorder.
// ---------------------------------------------------------------------------
__device__ __forceinline__ float slapy2f(float x, float y) {
    float xa = fabsf(x), ya = fabsf(y);
    float w = fmaxf(xa, ya), z = fminf(xa, ya);
    if (z == 0.f) return w;
    float t = FDIV(z, w);
    return FMUL(w, sqrtf(FADD(1.f, FMUL(t, t))));
}

__device__ __forceinline__ void slartgf(float f, float g, float& c, float& s,
                                        float& r) {
    if (g == 0.f) {
        c = 1.f; s = 0.f; r = f;
    } else if (f == 0.f) {
        c = 0.f; s = copysignf(1.f, g); r = fabsf(g);
    } else {
        float d = sqrtf(FADD(FMUL(f, f), FMUL(g, g)));
        float p = FDIV(1.f, d);
        c = FMUL(fabsf(f), p);
        s = FMUL(g, copysignf(p, f));
        r = copysignf(d, f);
    }
}

__device__ void slaev2f(float a, float b, float c0, float& rt1, float& rt2,
                        float& cs1, float& sn1) {
    float sm = FADD(a, c0);
    float df = FSUB(a, c0);
    float adf = fabsf(df);
    float tb = FADD(b, b);
    float ab = fabsf(tb);
    float acmx, acmn;
    if (fabsf(a) > fabsf(c0)) { acmx = a; acmn = c0; }
    else { acmx = c0; acmn = a; }
    float rt;
    if (adf > ab) {
        float t = FDIV(ab, adf);
        rt = FMUL(adf, sqrtf(FADD(1.f, FMUL(t, t))));
    } else if (adf < ab) {
        float t = FDIV(adf, ab);
        rt = FMUL(ab, sqrtf(FADD(1.f, FMUL(t, t))));
    } else {
        rt = FMUL(ab, sqrtf(2.f));
    }
    int sgn1;
    if (sm < 0.f) {
        rt1 = FMUL(0.5f, FSUB(sm, rt)); sgn1 = -1;
        rt2 = FSUB(FMUL(FDIV(acmx, rt1), acmn), FMUL(FDIV(b, rt1), b));
    } else if (sm > 0.f) {
        rt1 = FMUL(0.5f, FADD(sm, rt)); sgn1 = 1;
        rt2 = FSUB(FMUL(FDIV(acmx, rt1), acmn), FMUL(FDIV(b, rt1), b));
    } else {
        rt1 = FMUL(0.5f, rt); rt2 = FMUL(-0.5f, rt); sgn1 = 1;
    }
    int sgn2;
    float cs;
    if (df >= 0.f) { cs = FADD(df, rt); sgn2 = 1; }
    else { cs = FSUB(df, rt); sgn2 = -1; }
    float acs = fabsf(cs);
    if (acs > ab) {
        float ct = FDIV(-tb, cs);
        sn1 = FDIV(1.f, sqrtf(FADD(1.f, FMUL(ct, ct))));
        cs1 = FMUL(ct, sn1);
    } else {
        if (ab == 0.f) { cs1 = 1.f; sn1 = 0.f; }
        else {
            float tn = FDIV(-cs, tb);
            cs1 = FDIV(1.f, sqrtf(FADD(1.f, FMUL(tn, tn))));
            sn1 = FMUL(tn, cs1);
        }
    }
    if (sgn1 == sgn2) { float tau = cs1; cs1 = -sn1; sn1 = tau; }
}

// Register-resident index helpers.
__device__ __forceinline__ float sel3(int i, float v1, float v2, float v3) {
    return i == 1 ? v1 : (i == 2 ? v2 : v3);
}
__device__ __forceinline__ float sel2(int i, float v1, float v2) {
    return i == 1 ? v1 : v2;
}
#define SETD(i, x) do { float _x = (x); if ((i) == 1) d1 = _x; \
                        else if ((i) == 2) d2 = _x; else d3 = _x; } while (0)
#define SETE(i, x) do { float _x = (x); if ((i) == 1) e1 = _x; \
                        else e2 = _x; } while (0)

#define ROT12(c, s) do { float _t; \
    _t = z12; z12 = FSUB(FMUL(c, _t), FMUL(s, z11)); z11 = FADD(FMUL(s, _t), FMUL(c, z11)); \
    _t = z22; z22 = FSUB(FMUL(c, _t), FMUL(s, z21)); z21 = FADD(FMUL(s, _t), FMUL(c, z21)); \
    _t = z32; z32 = FSUB(FMUL(c, _t), FMUL(s, z31)); z31 = FADD(FMUL(s, _t), FMUL(c, z31)); \
} while (0)
#define ROT23(c, s) do { float _t; \
    _t = z13; z13 = FSUB(FMUL(c, _t), FMUL(s, z12)); z12 = FADD(FMUL(s, _t), FMUL(c, z12)); \
    _t = z23; z23 = FSUB(FMUL(c, _t), FMUL(s, z22)); z22 = FADD(FMUL(s, _t), FMUL(c, z22)); \
    _t = z33; z33 = FSUB(FMUL(c, _t), FMUL(s, z32)); z32 = FADD(FMUL(s, _t), FMUL(c, z32)); \
} while (0)
#define MROTA(c, s) do { float _t; \
    _t = z11; z11 = FSUB(FMUL(c, _t), FMUL(s, z12)); z12 = FADD(FMUL(s, _t), FMUL(c, z12)); \
    _t = z21; z21 = FSUB(FMUL(c, _t), FMUL(s, z22)); z22 = FADD(FMUL(s, _t), FMUL(c, z22)); \
    _t = z31; z31 = FSUB(FMUL(c, _t), FMUL(s, z32)); z32 = FADD(FMUL(s, _t), FMUL(c, z32)); \
} while (0)
#define MROTB(c, s) do { float _t; \
    _t = z12; z12 = FSUB(FMUL(c, _t), FMUL(s, z13)); z13 = FADD(FMUL(s, _t), FMUL(c, z13)); \
    _t = z22; z22 = FSUB(FMUL(c, _t), FMUL(s, z23)); z23 = FADD(FMUL(s, _t), FMUL(c, z23)); \
    _t = z32; z32 = FSUB(FMUL(c, _t), FMUL(s, z33)); z33 = FADD(FMUL(s, _t), FMUL(c, z33)); \
} while (0)
#define SWAPC12() do { float _t; _t = z11; z11 = z12; z12 = _t; \
    _t = z21; z21 = z22; z22 = _t; _t = z31; z31 = z32; z32 = _t; } while (0)
#define SWAPC13() do { float _t; _t = z11; z11 = z13; z13 = _t; \
    _t = z21; z21 = z23; z23 = _t; _t = z31; z31 = z33; z33 = _t; } while (0)
#define SWAPC23() do { float _t; _t = z12; z12 = z13; z13 = _t; \
    _t = z22; z22 = z23; z23 = _t; _t = z32; z32 = z33; z33 = _t; } while (0)

__device__ __forceinline__ void cov_acc(float4 q, float px, float py, float pz,
                                        float& a00, float& a10, float& a20,
                                        float& a11, float& a21, float& a22) {
    float dx = FSUB(q.x, px);
    float dy = FSUB(q.y, py);
    float dz = FSUB(q.z, pz);
    a00 = FADD(a00, FMUL(dx, dx));
    a10 = FADD(a10, FMUL(dx, dy));
    a20 = FADD(a20, FMUL(dx, dz));
    a11 = FADD(a11, FMUL(dy, dy));
    a21 = FADD(a21, FMUL(dy, dz));
    a22 = FADD(a22, FMUL(dz, dz));
}

// Deflation tests (key heuristic; perf-only if wrong).
__device__ __forceinline__ bool small_e(float e, float da, float db) {
    float t = fabsf(e);
    if (t == 0.f) return true;
    return t <= FMUL(FMUL(sqrtf(fabsf(da)), sqrtf(fabsf(db))), EPSF);
}
__device__ __forceinline__ bool small_e2(float e, float da, float db) {
    float t = FMUL(e, e);
    return t <= FADD(FMUL(FMUL(EPS2F, fabsf(da)), fabsf(db)), SAFMINF);
}

// ---------------------------------------------------------------------------
// Fused kernel: cov + ssytd2 -> block-local bucket sort (shared mem) ->
// ssteqr('I') + sormtr on path-homogeneous warps. Solver bits FROZEN.
// Grid shaped 1-block-per-SM (BLK=224, grid=147) for zero idle SMs.
// ---------------------------------------------------------------------------
__global__ void __launch_bounds__(BLK, 1)
fused_kernel(const int* __restrict__ edge_src,
             const int* __restrict__ num_neighbors,
             float* __restrict__ out, int n, int k) {
    __shared__ float s_rec[7][BLK];   // d1,d2,d3,e1,e2,tau1,v3 (sorted order)
    __shared__ int s_gid[BLK];
    __shared__ int s_cnt[NBKT];
    __shared__ int s_off[NBKT];

    int t = threadIdx.x;
    if (t < NBKT) s_cnt[t] = 0;
    __syncthreads();

    int gi = blockIdx.x * BLK + t;
    int key = 0, rank = 0;
    bool active = false;
    float d1, d2, d3, e1, e2, tau1 = 0.f, v3 = 0.f;

    if (gi < n) {
        if (num_neighbors[gi] <= 1) {
            float* o = out + (long long)gi * 9;
#pragma unroll
            for (int j = 0; j < 9; j++) o[j] = 0.f;
        } else {
            active = true;
            // ============ covariance (frozen arithmetic order) ===========
            float4 pc = g_pos4[gi];
            float px = pc.x, py = pc.y, pz = pc.z;
            float a00 = 0.f, a10 = 0.f, a20 = 0.f;
            float a11 = 0.f, a21 = 0.f, a22 = 0.f;
            const int4* es4 = (const int4*)(edge_src + (long long)gi * k);
#pragma unroll 8
            for (int j = 0; j < k / 4; j++) {
                int4 s4 = es4[j];
                float4 q0 = __ldg(&g_pos4[s4.x]);
                float4 q1 = __ldg(&g_pos4[s4.y]);
                float4 q2 = __ldg(&g_pos4[s4.z]);
                float4 q3 = __ldg(&g_pos4[s4.w]);
                cov_acc(q0, px, py, pz, a00, a10, a20, a11, a21, a22);
                cov_acc(q1, px, py, pz, a00, a10, a20, a11, a21, a22);
                cov_acc(q2, px, py, pz, a00, a10, a20, a11, a21, a22);
                cov_acc(q3, px, py, pz, a00, a10, a20, a11, a21, a22);
            }

            // ============ SSYTD2 (lower), n=3 — FROZEN ============
            {
                float alpha = a10;
                float x = a20;
                if (x == 0.f) {
                    tau1 = 0.f;
                    e1 = alpha;
                } else {
                    float beta = -copysignf(slapy2f(alpha, x), alpha);
                    tau1 = FDIV(FSUB(beta, alpha), beta);
                    float rcp = FDIV(1.f, FSUB(alpha, beta));
                    v3 = FMUL(x, rcp);
                    e1 = beta;
                    float w1 = FADD(FMUL(tau1, a11), FMUL(tau1, FMUL(a21, v3)));
                    float w2 = FADD(FMUL(tau1, a21), FMUL(FMUL(tau1, v3), a22));
                    float dot = FADD(w1, FMUL(w2, v3));
                    float al2 = -FMUL(FMUL(0.5f, tau1), dot);
                    w1 = FADD(w1, al2);
                    w2 = FADD(w2, FMUL(al2, v3));
                    a11 = FADD(FADD(a11, -w1), -w1);
                    a21 = FADD(FADD(a21, FMUL(v3, -w1)), -w2);
                    a22 = FADD(FADD(a22, FMUL(v3, -w2)), FMUL(w2, -v3));
                }
                e2 = a21;
                d1 = a00; d2 = a11; d3 = a22;
            }

            // ============ path key (scheduling only) ============
            int m = 3;
            if (small_e(e1, d1, d2)) m = 1;
            else if (small_e(e2, d2, d3)) m = 2;

            int ql, cse;
            if (m == 1) {
                if (small_e(e2, d2, d3)) {
                    ql = 0; cse = 3;
                } else {
                    ql = (fabsf(d3) < fabsf(d2)) ? 0 : 1;
                    cse = small_e2(e2, ql ? d2 : d3, ql ? d3 : d2) ? 0 : 1;
                }
            } else if (m == 2) {
                ql = (fabsf(d2) < fabsf(d1)) ? 0 : 1;
                cse = small_e2(e1, ql ? d1 : d2, ql ? d2 : d1) ? 0 : 1;
            } else {
                ql = (fabsf(d3) < fabsf(d1)) ? 0 : 1;
                if (ql) {
                    if (small_e2(e1, d1, d2)) cse = 0;
                    else if (small_e2(e2, d2, d3)) cse = 1;
                    else cse = 2;
                } else {
                    if (small_e2(e2, d3, d2)) cse = 0;
                    else if (small_e2(e1, d2, d1)) cse = 1;
                    else cse = 2;
                }
            }
            key = ((m - 1) << 3) + (ql << 2) + cse;   // 0..26 < NBKT
            rank = atomicAdd(&s_cnt[key], 1);
        }
    }
    __syncthreads();

    if (t == 0) {
        int run = 0;
#pragma unroll
        for (int b = 0; b < NBKT; b++) {
            s_off[b] = run;
            run += s_cnt[b];
        }
    }
    __syncthreads();

    if (active) {
        int pos = s_off[key] + rank;
        s_rec[0][pos] = d1;
        s_rec[1][pos] = d2;
        s_rec[2][pos] = d3;
        s_rec[3][pos] = e1;
        s_rec[4][pos] = e2;
        s_rec[5][pos] = tau1;
        s_rec[6][pos] = v3;
        s_gid[pos] = gi;
    }
    int total = s_off[NBKT - 1] + s_cnt[NBKT - 1];
    __syncthreads();

    if (t >= total) return;

    // Load t-th sorted record (bit-identical values; scheduling only).
    d1 = s_rec[0][t];
    d2 = s_rec[1][t];
    d3 = s_rec[2][t];
    e1 = s_rec[3][t];
    e2 = s_rec[4][t];
    tau1 = s_rec[5][t];
    v3 = s_rec[6][t];
    int ogi = s_gid[t];

    // ================= SSTEQR('I'), n=3 — FROZEN (R9 unified) =============
    const float eps = EPSF;
    const float eps2 = FMUL(eps, eps);
    const float safmin = SAFMINF;
    const int nmaxit = 90;
    int jtot = 0;

    float z11 = 1.f, z21 = 0.f, z31 = 0.f;
    float z12 = 0.f, z22 = 1.f, z32 = 0.f;
    float z13 = 0.f, z23 = 0.f, z33 = 1.f;

    int l1 = 1;
    while (l1 <= 3) {
        if (l1 > 1) SETE(l1 - 1, 0.f);
        int m = 3;
        for (int mm = l1; mm <= 2; mm++) {
            float tst = fabsf(sel2(mm, e1, e2));
            if (tst == 0.f) { m = mm; break; }
            if (tst <= FMUL(FMUL(sqrtf(fabsf(sel3(mm, d1, d2, d3))),
                                 sqrtf(fabsf(sel3(mm + 1, d1, d2, d3)))),
                            eps)) {
                SETE(mm, 0.f);
                m = mm; break;
            }
        }
        int l = l1, lsv = l, lend = m, lendsv = lend;
        l1 = m + 1;
        if (lend == l) continue;

        float anorm = 0.f;
        for (int i = l; i <= lend; i++)
            anorm = fmaxf(anorm, fabsf(sel3(i, d1, d2, d3)));
        for (int i = l; i <= lend - 1; i++)
            anorm = fmaxf(anorm, fabsf(sel2(i, e1, e2)));
        if (anorm == 0.f) continue;

        if (fabsf(sel3(lend, d1, d2, d3)) < fabsf(sel3(l, d1, d2, d3))) {
            lend = lsv; l = lendsv;
        }

        bool ql = (lend > l);
        int lv = ql ? l : 4 - l;
        int lendv = ql ? lend : 4 - lend;

        while (1) {
            int m2 = lendv;
            if (lv != lendv) {
                for (int mm = lv; mm <= lendv - 1; mm++) {
                    float emm = sel2(ql ? mm : 3 - mm, e1, e2);
                    float tst = FMUL(emm, emm);
                    float dmm = sel3(ql ? mm : 4 - mm, d1, d2, d3);
                    float dmm1 = sel3(ql ? mm + 1 : 3 - mm, d1, d2, d3);
                    if (tst <= FADD(FMUL(FMUL(eps2, fabsf(dmm)), fabsf(dmm1)),
                                    safmin)) {
                        m2 = mm; break;
                    }
                }
            }
            if (m2 < lendv) SETE(ql ? m2 : 3 - m2, 0.f);
            float p = sel3(ql ? lv : 4 - lv, d1, d2, d3);
            if (m2 == lv) {
                lv = lv + 1;
                if (lv <= lendv) continue;
                break;
            }
            if (m2 == lv + 1) {
                float rt1, rt2, c, s;
                float bb = sel2(ql ? lv : 3 - lv, e1, e2);
                float aa, cc;
                if (ql) {
                    aa = sel3(lv, d1, d2, d3);
                    cc = sel3(lv + 1, d1, d2, d3);
                } else {
                    aa = sel3(3 - lv, d1, d2, d3);
                    cc = sel3(4 - lv, d1, d2, d3);
                }
                slaev2f(aa, bb, cc, rt1, rt2, c, s);
                if ((ql && lv == 1) || (!ql && lv == 2)) { ROT12(c, s); }
                else { ROT23(c, s); }
                if (ql) {
                    SETD(lv, rt1); SETD(lv + 1, rt2); SETE(lv, 0.f);
                } else {
                    SETD(3 - lv, rt1); SETD(4 - lv, rt2); SETE(3 - lv, 0.f);
                }
                lv = lv + 2;
                if (lv <= lendv) continue;
                break;
            }
            if (jtot == nmaxit) break;
            jtot++;
            float vd1 = ql ? d1 : d3, vd3 = ql ? d3 : d1;
            float ve1 = ql ? e1 : e2, ve2 = ql ? e2 : e1;
            float g = FDIV(FSUB(d2, p), FMUL(2.f, ve1));
            float r = slapy2f(g, 1.f);
            g = FADD(FSUB(vd3, p), FDIV(ve1, FADD(g, copysignf(r, g))));
            float s = 1.f, c = 1.f;
            p = 0.f;
            float wc1, wc2, ws1, ws2;
            {   // virtual i = 2
                float f = FMUL(s, ve2);
                float b = FMUL(c, ve2);
                slartgf(g, f, c, s, r);
                g = FSUB(vd3, p);
                r = FADD(FMUL(FSUB(d2, g), s), FMUL(FMUL(2.f, c), b));
                p = FMUL(s, r);
                vd3 = FADD(g, p);
                g = FSUB(FMUL(c, r), b);
                wc2 = c; ws2 = -s;
            }
            {   // virtual i = 1
                float f = FMUL(s, ve1);
                float b = FMUL(c, ve1);
                slartgf(g, f, c, s, r);
                ve2 = r;
                g = FSUB(d2, p);
                r = FADD(FMUL(FSUB(vd1, g), s), FMUL(FMUL(2.f, c), b));
                p = FMUL(s, r);
                d2 = FADD(g, p);
                g = FSUB(FMUL(c, r), b);
                wc1 = c; ws1 = -s;
            }
            if (wc2 != 1.f || ws2 != 0.f) {
                if (ql) { ROT23(wc2, ws2); } else { MROTA(wc2, ws2); }
            }
            if (wc1 != 1.f || ws1 != 0.f) {
                if (ql) { ROT12(wc1, ws1); } else { MROTB(wc1, ws1); }
            }
            vd1 = FSUB(vd1, p);
            ve1 = g;
            if (ql) { d1 = vd1; d3 = vd3; e1 = ve1; e2 = ve2; }
            else    { d3 = vd1; d1 = vd3; e2 = ve1; e1 = ve2; }
        }
    }

    // selection sort (ascending, column swaps)
    {
        int kk = 1; float p = d1;
        if (d2 < p) { kk = 2; p = d2; }
        if (d3 < p) { kk = 3; p = d3; }
        if (kk == 2) { d2 = d1; d1 = p; SWAPC12(); }
        else if (kk == 3) { d3 = d1; d1 = p; SWAPC13(); }
    }
    {
        if (d3 < d2) { float p = d2; d2 = d3; d3 = p; SWAPC23(); }
    }

    // SORMTR: Z := H(1)*Z
    if (tau1 != 0.f) {
        float w, tt;
        w = FADD(z21, FMUL(z31, v3)); tt = FMUL(-tau1, w);
        z21 = FADD(z21, tt); z31 = FADD(z31, FMUL(v3, tt));
        w = FADD(z22, FMUL(z32, v3)); tt = FMUL(-tau1, w);
        z22 = FADD(z22, tt); z32 = FADD(z32, FMUL(v3, tt));
        w = FADD(z23, FMUL(z33, v3)); tt = FMUL(-tau1, w);
        z23 = FADD(z23, tt); z33 = FADD(z33, FMUL(v3, tt));
    }

    float* o = out + (long long)ogi * 9;
    o[0] = z11; o[1] = z21; o[2] = z31;
    o[3] = z12; o[4] = z22; o[5] = z32;
    o[6] = z13; o[7] = z23; o[8] = z33;
}

// ---------------------------------------------------------------------------
// Launch
// ---------------------------------------------------------------------------
extern "C" void kernel_launch(void* const* d_in, const int* in_sizes, int n_in,
                              void* d_out, int out_size) {
    const float* pos = (const float*)d_in[0];
    const int* edge_src = (const int*)d_in[1];
    // d_in[2] = edge_dst: unused (edge_dst == repeat(arange(n), k))
    const int* num_neighbors = (const int*)d_in[3];

    int n = in_sizes[3];
    int k = in_sizes[1] / n;

    pad_kernel<<<(n + 255) / 256, 256>>>(pos, n);
    fused_kernel<<<(n + BLK - 1) / BLK, BLK>>>(edge_src, num_neighbors,
                                               (float*)d_out, n, k);
}

// round 14
// speedup vs baseline: 2.5910x; 1.1987x over previous
#include <cuda_runtime.h>
#include <math.h>

#define MAXN 32768
#define NBKT 32
#define BLK 224   // 7 warps; grid 147 = 1 block/SM

#define FADD __fadd_rn
#define FSUB __fsub_rn
#define FMUL __fmul_rn
#define FDIV __fdiv_rn

#define EPSF   5.9604644775390625e-08f     // 2^-24
#define EPS2F  (EPSF * EPSF)
#define SAFMINF 1.1754943508222875e-38f    // 2^-126

// 16B-aligned padded positions: one LDG.128 per neighbor gather.
__device__ float4 g_pos4[MAXN];

// ---------------------------------------------------------------------------
// Kernel A: pad pos[3*i..3*i+2] -> g_pos4[i].
// ---------------------------------------------------------------------------
__global__ void pad_kernel(const float* __restrict__ pos, int n) {
    int i = blockIdx.x * blockDim.x + threadIdx.x;
    if (i >= n) return;
    float4 p;
    p.x = pos[3 * i + 0];
    p.y = pos[3 * i + 1];
    p.z = pos[3 * i + 2];
    p.w = 0.f;
    g_pos4[i] = p;
}

// ---------------------------------------------------------------------------
// LAPACK fp32 helpers, netlib-expression-faithful (LAPACK >= 3.10).
// FROZEN: arithmetic validated at rel_err 3.4e-7 — do not reorder.
// ---------------------------------------------------------------------------
__device__ __forceinline__ float slapy2f(float x, float y) {
    float xa = fabsf(x), ya = fabsf(y);
    float w = fmaxf(xa, ya), z = fminf(xa, ya);
    if (z == 0.f) return w;
    float t = FDIV(z, w);
    return FMUL(w, sqrtf(FADD(1.f, FMUL(t, t))));
}

__device__ __forceinline__ void slartgf(float f, float g, float& c, float& s,
                                        float& r) {
    if (g == 0.f) {
        c = 1.f; s = 0.f; r = f;
    } else if (f == 0.f) {
        c = 0.f; s = copysignf(1.f, g); r = fabsf(g);
    } else {
        float d = sqrtf(FADD(FMUL(f, f), FMUL(g, g)));
        float p = FDIV(1.f, d);
        c = FMUL(fabsf(f), p);
        s = FMUL(g, copysignf(p, f));
        r = copysignf(d, f);
    }
}

__device__ void slaev2f(float a, float b, float c0, float& rt1, float& rt2,
                        float& cs1, float& sn1) {
    float sm = FADD(a, c0);
    float df = FSUB(a, c0);
    float adf = fabsf(df);
    float tb = FADD(b, b);
    float ab = fabsf(tb);
    float acmx, acmn;
    if (fabsf(a) > fabsf(c0)) { acmx = a; acmn = c0; }
    else { acmx = c0; acmn = a; }
    float rt;
    if (adf > ab) {
        float t = FDIV(ab, adf);
        rt = FMUL(adf, sqrtf(FADD(1.f, FMUL(t, t))));
    } else if (adf < ab) {
        float t = FDIV(adf, ab);
        rt = FMUL(ab, sqrtf(FADD(1.f, FMUL(t, t))));
    } else {
        rt = FMUL(ab, sqrtf(2.f));
    }
    int sgn1;
    if (sm < 0.f) {
        rt1 = FMUL(0.5f, FSUB(sm, rt)); sgn1 = -1;
        rt2 = FSUB(FMUL(FDIV(acmx, rt1), acmn), FMUL(FDIV(b, rt1), b));
    } else if (sm > 0.f) {
        rt1 = FMUL(0.5f, FADD(sm, rt)); sgn1 = 1;
        rt2 = FSUB(FMUL(FDIV(acmx, rt1), acmn), FMUL(FDIV(b, rt1), b));
    } else {
        rt1 = FMUL(0.5f, rt); rt2 = FMUL(-0.5f, rt); sgn1 = 1;
    }
    int sgn2;
    float cs;
    if (df >= 0.f) { cs = FADD(df, rt); sgn2 = 1; }
    else { cs = FSUB(df, rt); sgn2 = -1; }
    float acs = fabsf(cs);
    if (acs > ab) {
        float ct = FDIV(-tb, cs);
        sn1 = FDIV(1.f, sqrtf(FADD(1.f, FMUL(ct, ct))));
        cs1 = FMUL(ct, sn1);
    } else {
        if (ab == 0.f) { cs1 = 1.f; sn1 = 0.f; }
        else {
            float tn = FDIV(-cs, tb);
            cs1 = FDIV(1.f, sqrtf(FADD(1.f, FMUL(tn, tn))));
            sn1 = FMUL(tn, cs1);
        }
    }
    if (sgn1 == sgn2) { float tau = cs1; cs1 = -sn1; sn1 = tau; }
}

// Rotations on Z columns (hi-col form); M-variants are the exact QR mirrors.
#define ROT12(c, s) do { float _t; \
    _t = z12; z12 = FSUB(FMUL(c, _t), FMUL(s, z11)); z11 = FADD(FMUL(s, _t), FMUL(c, z11)); \
    _t = z22; z22 = FSUB(FMUL(c, _t), FMUL(s, z21)); z21 = FADD(FMUL(s, _t), FMUL(c, z21)); \
    _t = z32; z32 = FSUB(FMUL(c, _t), FMUL(s, z31)); z31 = FADD(FMUL(s, _t), FMUL(c, z31)); \
} while (0)
#define ROT23(c, s) do { float _t; \
    _t = z13; z13 = FSUB(FMUL(c, _t), FMUL(s, z12)); z12 = FADD(FMUL(s, _t), FMUL(c, z12)); \
    _t = z23; z23 = FSUB(FMUL(c, _t), FMUL(s, z22)); z22 = FADD(FMUL(s, _t), FMUL(c, z22)); \
    _t = z33; z33 = FSUB(FMUL(c, _t), FMUL(s, z32)); z32 = FADD(FMUL(s, _t), FMUL(c, z32)); \
} while (0)
#define MROTA(c, s) do { float _t; \
    _t = z11; z11 = FSUB(FMUL(c, _t), FMUL(s, z12)); z12 = FADD(FMUL(s, _t), FMUL(c, z12)); \
    _t = z21; z21 = FSUB(FMUL(c, _t), FMUL(s, z22)); z22 = FADD(FMUL(s, _t), FMUL(c, z22)); \
    _t = z31; z31 = FSUB(FMUL(c, _t), FMUL(s, z32)); z32 = FADD(FMUL(s, _t), FMUL(c, z32)); \
} while (0)
#define MROTB(c, s) do { float _t; \
    _t = z12; z12 = FSUB(FMUL(c, _t), FMUL(s, z13)); z13 = FADD(FMUL(s, _t), FMUL(c, z13)); \
    _t = z22; z22 = FSUB(FMUL(c, _t), FMUL(s, z23)); z23 = FADD(FMUL(s, _t), FMUL(c, z23)); \
    _t = z32; z32 = FSUB(FMUL(c, _t), FMUL(s, z33)); z33 = FADD(FMUL(s, _t), FMUL(c, z33)); \
} while (0)
#define SWAPC12() do { float _t; _t = z11; z11 = z12; z12 = _t; \
    _t = z21; z21 = z22; z22 = _t; _t = z31; z31 = z32; z32 = _t; } while (0)
#define SWAPC13() do { float _t; _t = z11; z11 = z13; z13 = _t; \
    _t = z21; z21 = z23; z23 = _t; _t = z31; z31 = z33; z33 = _t; } while (0)
#define SWAPC23() do { float _t; _t = z12; z12 = z13; z13 = _t; \
    _t = z22; z22 = z23; z23 = _t; _t = z32; z32 = z33; z33 = _t; } while (0)

__device__ __forceinline__ void cov_acc(float4 q, float px, float py, float pz,
                                        float& a00, float& a10, float& a20,
                                        float& a11, float& a21, float& a22) {
    float dx = FSUB(q.x, px);
    float dy = FSUB(q.y, py);
    float dz = FSUB(q.z, pz);
    a00 = FADD(a00, FMUL(dx, dx));
    a10 = FADD(a10, FMUL(dx, dy));
    a20 = FADD(a20, FMUL(dx, dz));
    a11 = FADD(a11, FMUL(dy, dy));
    a21 = FADD(a21, FMUL(dy, dz));
    a22 = FADD(a22, FMUL(dz, dz));
}

// Deflation tests (exact ssteqr expressions).
__device__ __forceinline__ bool small_e(float e, float da, float db) {
    float t = fabsf(e);
    if (t == 0.f) return true;
    return t <= FMUL(FMUL(sqrtf(fabsf(da)), sqrtf(fabsf(db))), EPSF);
}
__device__ __forceinline__ bool small_e2(float e, float da, float db) {
    float t = FMUL(e, e);
    return t <= FADD(FMUL(FMUL(EPS2F, fabsf(da)), fabsf(db)), SAFMINF);
}

// ---------------------------------------------------------------------------
// Fused kernel: cov + ssytd2 -> block-local bucket sort -> fully-specialized
// ssteqr('I') decision tree (constant indices) + sormtr. Arithmetic FROZEN.
// ---------------------------------------------------------------------------
__global__ void __launch_bounds__(BLK, 1)
fused_kernel(const int* __restrict__ edge_src,
             const int* __restrict__ num_neighbors,
             float* __restrict__ out, int n, int k) {
    __shared__ float s_rec[7][BLK];   // d1,d2,d3,e1,e2,tau1,v3 (sorted order)
    __shared__ int s_gid[BLK];
    __shared__ int s_cnt[NBKT];
    __shared__ int s_off[NBKT];

    int t = threadIdx.x;
    if (t < NBKT) s_cnt[t] = 0;
    __syncthreads();

    int gi = blockIdx.x * BLK + t;
    int key = 0, rank = 0;
    bool active = false;
    float d1, d2, d3, e1, e2, tau1 = 0.f, v3 = 0.f;

    if (gi < n) {
        if (num_neighbors[gi] <= 1) {
            float* o = out + (long long)gi * 9;
#pragma unroll
            for (int j = 0; j < 9; j++) o[j] = 0.f;
        } else {
            active = true;
            // ============ covariance (frozen arithmetic order) ===========
            float4 pc = g_pos4[gi];
            float px = pc.x, py = pc.y, pz = pc.z;
            float a00 = 0.f, a10 = 0.f, a20 = 0.f;
            float a11 = 0.f, a21 = 0.f, a22 = 0.f;
            const int4* es4 = (const int4*)(edge_src + (long long)gi * k);
#pragma unroll 8
            for (int j = 0; j < k / 4; j++) {
                int4 s4 = es4[j];
                float4 q0 = __ldg(&g_pos4[s4.x]);
                float4 q1 = __ldg(&g_pos4[s4.y]);
                float4 q2 = __ldg(&g_pos4[s4.z]);
                float4 q3 = __ldg(&g_pos4[s4.w]);
                cov_acc(q0, px, py, pz, a00, a10, a20, a11, a21, a22);
                cov_acc(q1, px, py, pz, a00, a10, a20, a11, a21, a22);
                cov_acc(q2, px, py, pz, a00, a10, a20, a11, a21, a22);
                cov_acc(q3, px, py, pz, a00, a10, a20, a11, a21, a22);
            }

            // ============ SSYTD2 (lower), n=3 — FROZEN ============
            {
                float alpha = a10;
                float x = a20;
                if (x == 0.f) {
                    tau1 = 0.f;
                    e1 = alpha;
                } else {
                    float beta = -copysignf(slapy2f(alpha, x), alpha);
                    tau1 = FDIV(FSUB(beta, alpha), beta);
                    float rcp = FDIV(1.f, FSUB(alpha, beta));
                    v3 = FMUL(x, rcp);
                    e1 = beta;
                    float w1 = FADD(FMUL(tau1, a11), FMUL(tau1, FMUL(a21, v3)));
                    float w2 = FADD(FMUL(tau1, a21), FMUL(FMUL(tau1, v3), a22));
                    float dot = FADD(w1, FMUL(w2, v3));
                    float al2 = -FMUL(FMUL(0.5f, tau1), dot);
                    w1 = FADD(w1, al2);
                    w2 = FADD(w2, FMUL(al2, v3));
                    a11 = FADD(FADD(a11, -w1), -w1);
                    a21 = FADD(FADD(a21, FMUL(v3, -w1)), -w2);
                    a22 = FADD(FADD(a22, FMUL(v3, -w2)), FMUL(w2, -v3));
                }
                e2 = a21;
                d1 = a00; d2 = a11; d3 = a22;
            }

            // ============ path key (scheduling only) ============
            int m = 3;
            if (small_e(e1, d1, d2)) m = 1;
            else if (small_e(e2, d2, d3)) m = 2;

            int ql, cse;
            if (m == 1) {
                if (small_e(e2, d2, d3)) {
                    ql = 0; cse = 3;
                } else {
                    ql = (fabsf(d3) < fabsf(d2)) ? 0 : 1;
                    cse = small_e2(e2, ql ? d2 : d3, ql ? d3 : d2) ? 0 : 1;
                }
            } else if (m == 2) {
                ql = (fabsf(d2) < fabsf(d1)) ? 0 : 1;
                cse = small_e2(e1, ql ? d1 : d2, ql ? d2 : d1) ? 0 : 1;
            } else {
                ql = (fabsf(d3) < fabsf(d1)) ? 0 : 1;
                if (ql) {
                    if (small_e2(e1, d1, d2)) cse = 0;
                    else if (small_e2(e2, d2, d3)) cse = 1;
                    else cse = 2;
                } else {
                    if (small_e2(e2, d3, d2)) cse = 0;
                    else if (small_e2(e1, d2, d1)) cse = 1;
                    else cse = 2;
                }
            }
            key = ((m - 1) << 3) + (ql << 2) + cse;   // 0..26 < NBKT
            rank = atomicAdd(&s_cnt[key], 1);
        }
    }
    __syncthreads();

    if (t == 0) {
        int run = 0;
#pragma unroll
        for (int b = 0; b < NBKT; b++) {
            s_off[b] = run;
            run += s_cnt[b];
        }
    }
    __syncthreads();

    if (active) {
        int pos = s_off[key] + rank;
        s_rec[0][pos] = d1;
        s_rec[1][pos] = d2;
        s_rec[2][pos] = d3;
        s_rec[3][pos] = e1;
        s_rec[4][pos] = e2;
        s_rec[5][pos] = tau1;
        s_rec[6][pos] = v3;
        s_gid[pos] = gi;
    }
    int total = s_off[NBKT - 1] + s_cnt[NBKT - 1];
    __syncthreads();

    if (t >= total) return;

    d1 = s_rec[0][t];
    d2 = s_rec[1][t];
    d3 = s_rec[2][t];
    e1 = s_rec[3][t];
    e2 = s_rec[4][t];
    tau1 = s_rec[5][t];
    v3 = s_rec[6][t];
    int ogi = s_gid[t];

    // ====== SSTEQR('I'), n=3 — fully specialized decision tree (FROZEN) ====
    float z11 = 1.f, z21 = 0.f, z31 = 0.f;
    float z12 = 0.f, z22 = 1.f, z32 = 0.f;
    float z13 = 0.f, z23 = 0.f, z33 = 1.f;

    // Top-level split (slanst-eps test, exact scan order)
    bool blk13 = false, blk12 = false, blk23 = false;
    if (small_e(e1, d1, d2)) {
        e1 = 0.f;
        if (small_e(e2, d2, d3)) e2 = 0.f;
        else blk23 = true;
    } else if (small_e(e2, d2, d3)) {
        e2 = 0.f;
        blk12 = true;
    } else {
        blk13 = true;
    }

    if (blk13) {
        // ----- block [1,3] -----
        float anorm = fmaxf(fmaxf(fmaxf(fabsf(d1), fabsf(d2)), fabsf(d3)),
                            fmaxf(fabsf(e1), fabsf(e2)));
        if (anorm != 0.f) {
            bool ql = !(fabsf(d3) < fabsf(d1));
            float vd1, vd3, ve1, ve2;
            float vd2 = d2;
            if (ql) { vd1 = d1; vd3 = d3; ve1 = e1; ve2 = e2; }
            else    { vd1 = d3; vd3 = d1; ve1 = e2; ve2 = e1; }
            int jtot = 0;
            int lv = 1;
            while (1) {
                if (lv == 1) {
                    if (small_e2(ve1, vd1, vd2)) { ve1 = 0.f; lv = 2; continue; }
                    if (small_e2(ve2, vd2, vd3)) {
                        // m2 = 2 < lendv: zero e, then 2x2 on virtual (1,2)
                        ve2 = 0.f;
                        float rt1, rt2, c, s;
                        if (ql) {
                            slaev2f(vd1, ve1, vd2, rt1, rt2, c, s);
                            ROT12(c, s);
                            vd1 = rt1; vd2 = rt2;
                        } else {
                            slaev2f(vd2, ve1, vd1, rt1, rt2, c, s);
                            ROT23(c, s);
                            vd2 = rt1; vd1 = rt2;
                        }
                        ve1 = 0.f;
                        break;  // lv -> 3 == lendv: trivial
                    }
                    // m2 = 3: implicit-shift iteration (R9 virtual body)
                    if (jtot == 90) break;
                    jtot++;
                    float p = vd1;
                    float g = FDIV(FSUB(vd2, p), FMUL(2.f, ve1));
                    float r = slapy2f(g, 1.f);
                    g = FADD(FSUB(vd3, p), FDIV(ve1, FADD(g, copysignf(r, g))));
                    float s = 1.f, c = 1.f;
                    p = 0.f;
                    float wc1, wc2, ws1, ws2;
                    {   // virtual i = 2
                        float f = FMUL(s, ve2);
                        float b = FMUL(c, ve2);
                        slartgf(g, f, c, s, r);
                        g = FSUB(vd3, p);
                        r = FADD(FMUL(FSUB(vd2, g), s), FMUL(FMUL(2.f, c), b));
                        p = FMUL(s, r);
                        vd3 = FADD(g, p);
                        g = FSUB(FMUL(c, r), b);
                        wc2 = c; ws2 = -s;
                    }
                    {   // virtual i = 1
                        float f = FMUL(s, ve1);
                        float b = FMUL(c, ve1);
                        slartgf(g, f, c, s, r);
                        ve2 = r;
                        g = FSUB(vd2, p);
                        r = FADD(FMUL(FSUB(vd1, g), s), FMUL(FMUL(2.f, c), b));
                        p = FMUL(s, r);
                        vd2 = FADD(g, p);
                        g = FSUB(FMUL(c, r), b);
                        wc1 = c; ws1 = -s;
                    }
                    if (wc2 != 1.f || ws2 != 0.f) {
                        if (ql) { ROT23(wc2, ws2); } else { MROTA(wc2, ws2); }
                    }
                    if (wc1 != 1.f || ws1 != 0.f) {
                        if (ql) { ROT12(wc1, ws1); } else { MROTB(wc1, ws1); }
                    }
                    vd1 = FSUB(vd1, p);
                    ve1 = g;
                    continue;
                }
                // lv == 2
                if (small_e2(ve2, vd2, vd3)) { ve2 = 0.f; break; }
                {
                    float rt1, rt2, c, s;
                    if (ql) {
                        slaev2f(vd2, ve2, vd3, rt1, rt2, c, s);
                        ROT23(c, s);
                        vd2 = rt1; vd3 = rt2;
                    } else {
                        slaev2f(vd3, ve2, vd2, rt1, rt2, c, s);
                        ROT12(c, s);
                        vd3 = rt1; vd2 = rt2;
                    }
                    ve2 = 0.f;
                }
                break;
            }
            if (ql) { d1 = vd1; d2 = vd2; d3 = vd3; }
            else    { d3 = vd1; d2 = vd2; d1 = vd3; }
        }
    } else if (blk12) {
        // ----- block [1,2] -----
        float anorm = fmaxf(fmaxf(fabsf(d1), fabsf(d2)), fabsf(e1));
        if (anorm != 0.f) {
            bool qlb = !(fabsf(d2) < fabsf(d1));
            bool sml = qlb ? small_e2(e1, d1, d2) : small_e2(e1, d2, d1);
            if (sml) {
                e1 = 0.f;
            } else {
                float rt1, rt2, c, s;
                slaev2f(d1, e1, d2, rt1, rt2, c, s);
                ROT12(c, s);
                d1 = rt1; d2 = rt2; e1 = 0.f;
            }
        }
    } else if (blk23) {
        // ----- block [2,3] -----
        float anorm = fmaxf(fmaxf(fabsf(d2), fabsf(d3)), fabsf(e2));
        if (anorm != 0.f) {
            bool qlb = !(fabsf(d3) < fabsf(d2));
            bool sml = qlb ? small_e2(e2, d2, d3) : small_e2(e2, d3, d2);
            if (sml) {
                e2 = 0.f;
            } else {
                float rt1, rt2, c, s;
                slaev2f(d2, e2, d3, rt1, rt2, c, s);
                ROT23(c, s);
                d2 = rt1; d3 = rt2; e2 = 0.f;
            }
        }
    }

    // selection sort (ascending, column swaps)
    {
        int kk = 1; float p = d1;
        if (d2 < p) { kk = 2; p = d2; }
        if (d3 < p) { kk = 3; p = d3; }
        if (kk == 2) { d2 = d1; d1 = p; SWAPC12(); }
        else if (kk == 3) { d3 = d1; d1 = p; SWAPC13(); }
    }
    {
        if (d3 < d2) { float p = d2; d2 = d3; d3 = p; SWAPC23(); }
    }

    // SORMTR: Z := H(1)*Z
    if (tau1 != 0.f) {
        float w, tt;
        w = FADD(z21, FMUL(z31, v3)); tt = FMUL(-tau1, w);
        z21 = FADD(z21, tt); z31 = FADD(z31, FMUL(v3, tt));
        w = FADD(z22, FMUL(z32, v3)); tt = FMUL(-tau1, w);
        z22 = FADD(z22, tt); z32 = FADD(z32, FMUL(v3, tt));
        w = FADD(z23, FMUL(z33, v3)); tt = FMUL(-tau1, w);
        z23 = FADD(z23, tt); z33 = FADD(z33, FMUL(v3, tt));
    }

    float* o = out + (long long)ogi * 9;
    o[0] = z11; o[1] = z21; o[2] = z31;
    o[3] = z12; o[4] = z22; o[5] = z32;
    o[6] = z13; o[7] = z23; o[8] = z33;
}

// ---------------------------------------------------------------------------
// Launch
// ---------------------------------------------------------------------------
extern "C" void kernel_launch(void* const* d_in, const int* in_sizes, int n_in,
                              void* d_out, int out_size) {
    const float* pos = (const float*)d_in[0];
    const int* edge_src = (const int*)d_in[1];
    // d_in[2] = edge_dst: unused (edge_dst == repeat(arange(n), k))
    const int* num_neighbors = (const int*)d_in[3];

    int n = in_sizes[3];
    int k = in_sizes[1] / n;

    pad_kernel<<<(n + 255) / 256, 256>>>(pos, n);
    fused_kernel<<<(n + BLK - 1) / BLK, BLK>>>(edge_src, num_neighbors,
                                               (float*)d_out, n, k);
}

// round 15
// speedup vs baseline: 2.6216x; 1.0118x over previous
#include <cuda_runtime.h>
#include <math.h>

#define MAXN 32768
#define NBKT 48
#define BLK 224   // 7 warps; grid 147 = 1 block/SM

#define FADD __fadd_rn
#define FSUB __fsub_rn
#define FMUL __fmul_rn
#define FDIV __fdiv_rn

#define EPSF   5.9604644775390625e-08f     // 2^-24
#define EPS2F  (EPSF * EPSF)
#define SAFMINF 1.1754943508222875e-38f    // 2^-126

// 16B-aligned padded positions: one LDG.128 per neighbor gather.
__device__ float4 g_pos4[MAXN];

// ---------------------------------------------------------------------------
// Kernel A: pad pos[3*i..3*i+2] -> g_pos4[i].
// ---------------------------------------------------------------------------
__global__ void pad_kernel(const float* __restrict__ pos, int n) {
    int i = blockIdx.x * blockDim.x + threadIdx.x;
    if (i >= n) return;
    float4 p;
    p.x = pos[3 * i + 0];
    p.y = pos[3 * i + 1];
    p.z = pos[3 * i + 2];
    p.w = 0.f;
    g_pos4[i] = p;
}

// ---------------------------------------------------------------------------
// LAPACK fp32 helpers, netlib-expression-faithful (LAPACK >= 3.10).
// FROZEN: arithmetic validated at rel_err 3.4e-7 — do not reorder.
// ---------------------------------------------------------------------------
__device__ __forceinline__ float slapy2f(float x, float y) {
    float xa = fabsf(x), ya = fabsf(y);
    float w = fmaxf(xa, ya), z = fminf(xa, ya);
    if (z == 0.f) return w;
    float t = FDIV(z, w);
    return FMUL(w, sqrtf(FADD(1.f, FMUL(t, t))));
}

__device__ __forceinline__ void slartgf(float f, float g, float& c, float& s,
                                        float& r) {
    if (g == 0.f) {
        c = 1.f; s = 0.f; r = f;
    } else if (f == 0.f) {
        c = 0.f; s = copysignf(1.f, g); r = fabsf(g);
    } else {
        float d = sqrtf(FADD(FMUL(f, f), FMUL(g, g)));
        float p = FDIV(1.f, d);
        c = FMUL(fabsf(f), p);
        s = FMUL(g, copysignf(p, f));
        r = copysignf(d, f);
    }
}

__device__ void slaev2f(float a, float b, float c0, float& rt1, float& rt2,
                        float& cs1, float& sn1) {
    float sm = FADD(a, c0);
    float df = FSUB(a, c0);
    float adf = fabsf(df);
    float tb = FADD(b, b);
    float ab = fabsf(tb);
    float acmx, acmn;
    if (fabsf(a) > fabsf(c0)) { acmx = a; acmn = c0; }
    else { acmx = c0; acmn = a; }
    float rt;
    if (adf > ab) {
        float t = FDIV(ab, adf);
        rt = FMUL(adf, sqrtf(FADD(1.f, FMUL(t, t))));
    } else if (adf < ab) {
        float t = FDIV(adf, ab);
        rt = FMUL(ab, sqrtf(FADD(1.f, FMUL(t, t))));
    } else {
        rt = FMUL(ab, sqrtf(2.f));
    }
    int sgn1;
    if (sm < 0.f) {
        rt1 = FMUL(0.5f, FSUB(sm, rt)); sgn1 = -1;
        rt2 = FSUB(FMUL(FDIV(acmx, rt1), acmn), FMUL(FDIV(b, rt1), b));
    } else if (sm > 0.f) {
        rt1 = FMUL(0.5f, FADD(sm, rt)); sgn1 = 1;
        rt2 = FSUB(FMUL(FDIV(acmx, rt1), acmn), FMUL(FDIV(b, rt1), b));
    } else {
        rt1 = FMUL(0.5f, rt); rt2 = FMUL(-0.5f, rt); sgn1 = 1;
    }
    int sgn2;
    float cs;
    if (df >= 0.f) { cs = FADD(df, rt); sgn2 = 1; }
    else { cs = FSUB(df, rt); sgn2 = -1; }
    float acs = fabsf(cs);
    if (acs > ab) {
        float ct = FDIV(-tb, cs);
        sn1 = FDIV(1.f, sqrtf(FADD(1.f, FMUL(ct, ct))));
        cs1 = FMUL(ct, sn1);
    } else {
        if (ab == 0.f) { cs1 = 1.f; sn1 = 0.f; }
        else {
            float tn = FDIV(-cs, tb);
            cs1 = FDIV(1.f, sqrtf(FADD(1.f, FMUL(tn, tn))));
            sn1 = FMUL(tn, cs1);
        }
    }
    if (sgn1 == sgn2) { float tau = cs1; cs1 = -sn1; sn1 = tau; }
}

// Rotations on Z columns (hi-col form); M-variants are the exact QR mirrors.
#define ROT12(c, s) do { float _t; \
    _t = z12; z12 = FSUB(FMUL(c, _t), FMUL(s, z11)); z11 = FADD(FMUL(s, _t), FMUL(c, z11)); \
    _t = z22; z22 = FSUB(FMUL(c, _t), FMUL(s, z21)); z21 = FADD(FMUL(s, _t), FMUL(c, z21)); \
    _t = z32; z32 = FSUB(FMUL(c, _t), FMUL(s, z31)); z31 = FADD(FMUL(s, _t), FMUL(c, z31)); \
} while (0)
#define ROT23(c, s) do { float _t; \
    _t = z13; z13 = FSUB(FMUL(c, _t), FMUL(s, z12)); z12 = FADD(FMUL(s, _t), FMUL(c, z12)); \
    _t = z23; z23 = FSUB(FMUL(c, _t), FMUL(s, z22)); z22 = FADD(FMUL(s, _t), FMUL(c, z22)); \
    _t = z33; z33 = FSUB(FMUL(c, _t), FMUL(s, z32)); z32 = FADD(FMUL(s, _t), FMUL(c, z32)); \
} while (0)
#define MROTA(c, s) do { float _t; \
    _t = z11; z11 = FSUB(FMUL(c, _t), FMUL(s, z12)); z12 = FADD(FMUL(s, _t), FMUL(c, z12)); \
    _t = z21; z21 = FSUB(FMUL(c, _t), FMUL(s, z22)); z22 = FADD(FMUL(s, _t), FMUL(c, z22)); \
    _t = z31; z31 = FSUB(FMUL(c, _t), FMUL(s, z32)); z32 = FADD(FMUL(s, _t), FMUL(c, z32)); \
} while (0)
#define MROTB(c, s) do { float _t; \
    _t = z12; z12 = FSUB(FMUL(c, _t), FMUL(s, z13)); z13 = FADD(FMUL(s, _t), FMUL(c, z13)); \
    _t = z22; z22 = FSUB(FMUL(c, _t), FMUL(s, z23)); z23 = FADD(FMUL(s, _t), FMUL(c, z23)); \
    _t = z32; z32 = FSUB(FMUL(c, _t), FMUL(s, z33)); z33 = FADD(FMUL(s, _t), FMUL(c, z33)); \
} while (0)
#define SWAPC12() do { float _t; _t = z11; z11 = z12; z12 = _t; \
    _t = z21; z21 = z22; z22 = _t; _t = z31; z31 = z32; z32 = _t; } while (0)
#define SWAPC13() do { float _t; _t = z11; z11 = z13; z13 = _t; \
    _t = z21; z21 = z23; z23 = _t; _t = z31; z31 = z33; z33 = _t; } while (0)
#define SWAPC23() do { float _t; _t = z12; z12 = z13; z13 = _t; \
    _t = z22; z22 = z23; z23 = _t; _t = z32; z32 = z33; z33 = _t; } while (0)

__device__ __forceinline__ void cov_acc(float4 q, float px, float py, float pz,
                                        float& a00, float& a10, float& a20,
                                        float& a11, float& a21, float& a22) {
    float dx = FSUB(q.x, px);
    float dy = FSUB(q.y, py);
    float dz = FSUB(q.z, pz);
    a00 = FADD(a00, FMUL(dx, dx));
    a10 = FADD(a10, FMUL(dx, dy));
    a20 = FADD(a20, FMUL(dx, dz));
    a11 = FADD(a11, FMUL(dy, dy));
    a21 = FADD(a21, FMUL(dy, dz));
    a22 = FADD(a22, FMUL(dz, dz));
}

// Deflation tests (exact ssteqr expressions).
__device__ __forceinline__ bool small_e(float e, float da, float db) {
    float t = fabsf(e);
    if (t == 0.f) return true;
    return t <= FMUL(FMUL(sqrtf(fabsf(da)), sqrtf(fabsf(db))), EPSF);
}
__device__ __forceinline__ bool small_e2(float e, float da, float db) {
    float t = FMUL(e, e);
    return t <= FADD(FMUL(FMUL(EPS2F, fabsf(da)), fabsf(db)), SAFMINF);
}

// ---------------------------------------------------------------------------
// Fused kernel: cov + ssytd2 -> block-local bucket sort (key includes
// iteration-difficulty bits for shift-path nodes) -> specialized ssteqr
// decision tree + sormtr. Arithmetic FROZEN.
// ---------------------------------------------------------------------------
__global__ void __launch_bounds__(BLK, 1)
fused_kernel(const int* __restrict__ edge_src,
             const int* __restrict__ num_neighbors,
             float* __restrict__ out, int n, int k) {
    __shared__ float s_rec[7][BLK];   // d1,d2,d3,e1,e2,tau1,v3 (sorted order)
    __shared__ int s_gid[BLK];
    __shared__ int s_cnt[NBKT];
    __shared__ int s_off[NBKT];

    int t = threadIdx.x;
    if (t < NBKT) s_cnt[t] = 0;
    __syncthreads();

    int gi = blockIdx.x * BLK + t;
    int key = 0, rank = 0;
    bool active = false;
    float d1, d2, d3, e1, e2, tau1 = 0.f, v3 = 0.f;

    if (gi < n) {
        if (num_neighbors[gi] <= 1) {
            float* o = out + (long long)gi * 9;
#pragma unroll
            for (int j = 0; j < 9; j++) o[j] = 0.f;
        } else {
            active = true;
            // ============ covariance (frozen arithmetic order) ===========
            float4 pc = g_pos4[gi];
            float px = pc.x, py = pc.y, pz = pc.z;
            float a00 = 0.f, a10 = 0.f, a20 = 0.f;
            float a11 = 0.f, a21 = 0.f, a22 = 0.f;
            const int4* es4 = (const int4*)(edge_src + (long long)gi * k);
            if (k == 64) {
#pragma unroll
                for (int j = 0; j < 16; j++) {
                    int4 s4 = es4[j];
                    float4 q0 = __ldg(&g_pos4[s4.x]);
                    float4 q1 = __ldg(&g_pos4[s4.y]);
                    float4 q2 = __ldg(&g_pos4[s4.z]);
                    float4 q3 = __ldg(&g_pos4[s4.w]);
                    cov_acc(q0, px, py, pz, a00, a10, a20, a11, a21, a22);
                    cov_acc(q1, px, py, pz, a00, a10, a20, a11, a21, a22);
                    cov_acc(q2, px, py, pz, a00, a10, a20, a11, a21, a22);
                    cov_acc(q3, px, py, pz, a00, a10, a20, a11, a21, a22);
                }
            } else {
#pragma unroll 8
                for (int j = 0; j < k / 4; j++) {
                    int4 s4 = es4[j];
                    float4 q0 = __ldg(&g_pos4[s4.x]);
                    float4 q1 = __ldg(&g_pos4[s4.y]);
                    float4 q2 = __ldg(&g_pos4[s4.z]);
                    float4 q3 = __ldg(&g_pos4[s4.w]);
                    cov_acc(q0, px, py, pz, a00, a10, a20, a11, a21, a22);
                    cov_acc(q1, px, py, pz, a00, a10, a20, a11, a21, a22);
                    cov_acc(q2, px, py, pz, a00, a10, a20, a11, a21, a22);
                    cov_acc(q3, px, py, pz, a00, a10, a20, a11, a21, a22);
                }
            }

            // ============ SSYTD2 (lower), n=3 — FROZEN ============
            {
                float alpha = a10;
                float x = a20;
                if (x == 0.f) {
                    tau1 = 0.f;
                    e1 = alpha;
                } else {
                    float beta = -copysignf(slapy2f(alpha, x), alpha);
                    tau1 = FDIV(FSUB(beta, alpha), beta);
                    float rcp = FDIV(1.f, FSUB(alpha, beta));
                    v3 = FMUL(x, rcp);
                    e1 = beta;
                    float w1 = FADD(FMUL(tau1, a11), FMUL(tau1, FMUL(a21, v3)));
                    float w2 = FADD(FMUL(tau1, a21), FMUL(FMUL(tau1, v3), a22));
                    float dot = FADD(w1, FMUL(w2, v3));
                    float al2 = -FMUL(FMUL(0.5f, tau1), dot);
                    w1 = FADD(w1, al2);
                    w2 = FADD(w2, FMUL(al2, v3));
                    a11 = FADD(FADD(a11, -w1), -w1);
                    a21 = FADD(FADD(a21, FMUL(v3, -w1)), -w2);
                    a22 = FADD(FADD(a22, FMUL(v3, -w2)), FMUL(w2, -v3));
                }
                e2 = a21;
                d1 = a00; d2 = a11; d3 = a22;
            }

            // ============ path key (scheduling only) ============
            int m = 3;
            if (small_e(e1, d1, d2)) m = 1;
            else if (small_e(e2, d2, d3)) m = 2;

            int ql, cse;
            if (m == 1) {
                if (small_e(e2, d2, d3)) {
                    ql = 0; cse = 3;
                } else {
                    ql = (fabsf(d3) < fabsf(d2)) ? 0 : 1;
                    cse = small_e2(e2, ql ? d2 : d3, ql ? d3 : d2) ? 0 : 1;
                }
                key = (ql << 2) + cse;
            } else if (m == 2) {
                ql = (fabsf(d2) < fabsf(d1)) ? 0 : 1;
                cse = small_e2(e1, ql ? d1 : d2, ql ? d2 : d1) ? 0 : 1;
                key = 8 + (ql << 2) + cse;
            } else {
                ql = (fabsf(d3) < fabsf(d1)) ? 0 : 1;
                if (ql) {
                    if (small_e2(e1, d1, d2)) cse = 0;
                    else if (small_e2(e2, d2, d3)) cse = 1;
                    else cse = 2;
                } else {
                    if (small_e2(e2, d3, d2)) cse = 0;
                    else if (small_e2(e1, d2, d1)) cse = 1;
                    else cse = 2;
                }
                if (cse == 2) {
                    // shift path: add iteration-difficulty bits (exponent of
                    // distance-to-deflation ratio). Scheduling only.
                    float ve1 = ql ? e1 : e2;
                    float vda = ql ? d1 : d3;
                    float tst = ve1 * ve1;
                    float thr = EPS2F * fabsf(vda) * fabsf(d2) + SAFMINF;
                    float ratio = tst / thr;   // >= ~1 on this path
                    int ex = ((__float_as_int(ratio) >> 23) & 0xFF) - 127;
                    if (ex < 0) ex = 0;
                    int diff = ex / 18;
                    if (diff > 7) diff = 7;
                    key = 32 + (ql << 3) + diff;     // 32..47
                } else {
                    key = 16 + (ql << 2) + cse;      // 16..21
                }
            }
            rank = atomicAdd(&s_cnt[key], 1);
        }
    }
    __syncthreads();

    if (t == 0) {
        int run = 0;
#pragma unroll
        for (int b = 0; b < NBKT; b++) {
            s_off[b] = run;
            run += s_cnt[b];
        }
    }
    __syncthreads();

    if (active) {
        int pos = s_off[key] + rank;
        s_rec[0][pos] = d1;
        s_rec[1][pos] = d2;
        s_rec[2][pos] = d3;
        s_rec[3][pos] = e1;
        s_rec[4][pos] = e2;
        s_rec[5][pos] = tau1;
        s_rec[6][pos] = v3;
        s_gid[pos] = gi;
    }
    int total = s_off[NBKT - 1] + s_cnt[NBKT - 1];
    __syncthreads();

    if (t >= total) return;

    d1 = s_rec[0][t];
    d2 = s_rec[1][t];
    d3 = s_rec[2][t];
    e1 = s_rec[3][t];
    e2 = s_rec[4][t];
    tau1 = s_rec[5][t];
    v3 = s_rec[6][t];
    int ogi = s_gid[t];

    // ====== SSTEQR('I'), n=3 — fully specialized decision tree (FROZEN) ====
    float z11 = 1.f, z21 = 0.f, z31 = 0.f;
    float z12 = 0.f, z22 = 1.f, z32 = 0.f;
    float z13 = 0.f, z23 = 0.f, z33 = 1.f;

    bool blk13 = false, blk12 = false, blk23 = false;
    if (small_e(e1, d1, d2)) {
        e1 = 0.f;
        if (small_e(e2, d2, d3)) e2 = 0.f;
        else blk23 = true;
    } else if (small_e(e2, d2, d3)) {
        e2 = 0.f;
        blk12 = true;
    } else {
        blk13 = true;
    }

    if (blk13) {
        // ----- block [1,3] -----
        float anorm = fmaxf(fmaxf(fmaxf(fabsf(d1), fabsf(d2)), fabsf(d3)),
                            fmaxf(fabsf(e1), fabsf(e2)));
        if (anorm != 0.f) {
            bool ql = !(fabsf(d3) < fabsf(d1));
            float vd1, vd3, ve1, ve2;
            float vd2 = d2;
            if (ql) { vd1 = d1; vd3 = d3; ve1 = e1; ve2 = e2; }
            else    { vd1 = d3; vd3 = d1; ve1 = e2; ve2 = e1; }
            int jtot = 0;
            int lv = 1;
            while (1) {
                if (lv == 1) {
                    if (small_e2(ve1, vd1, vd2)) { ve1 = 0.f; lv = 2; continue; }
                    if (small_e2(ve2, vd2, vd3)) {
                        ve2 = 0.f;
                        float rt1, rt2, c, s;
                        if (ql) {
                            slaev2f(vd1, ve1, vd2, rt1, rt2, c, s);
                            ROT12(c, s);
                            vd1 = rt1; vd2 = rt2;
                        } else {
                            slaev2f(vd2, ve1, vd1, rt1, rt2, c, s);
                            ROT23(c, s);
                            vd2 = rt1; vd1 = rt2;
                        }
                        ve1 = 0.f;
                        break;
                    }
                    if (jtot == 90) break;
                    jtot++;
                    float p = vd1;
                    float g = FDIV(FSUB(vd2, p), FMUL(2.f, ve1));
                    float r = slapy2f(g, 1.f);
                    g = FADD(FSUB(vd3, p), FDIV(ve1, FADD(g, copysignf(r, g))));
                    float s = 1.f, c = 1.f;
                    p = 0.f;
                    float wc1, wc2, ws1, ws2;
                    {   // virtual i = 2
                        float f = FMUL(s, ve2);
                        float b = FMUL(c, ve2);
                        slartgf(g, f, c, s, r);
                        g = FSUB(vd3, p);
                        r = FADD(FMUL(FSUB(vd2, g), s), FMUL(FMUL(2.f, c), b));
                        p = FMUL(s, r);
                        vd3 = FADD(g, p);
                        g = FSUB(FMUL(c, r), b);
                        wc2 = c; ws2 = -s;
                    }
                    {   // virtual i = 1
                        float f = FMUL(s, ve1);
                        float b = FMUL(c, ve1);
                        slartgf(g, f, c, s, r);
                        ve2 = r;
                        g = FSUB(vd2, p);
                        r = FADD(FMUL(FSUB(vd1, g), s), FMUL(FMUL(2.f, c), b));
                        p = FMUL(s, r);
                        vd2 = FADD(g, p);
                        g = FSUB(FMUL(c, r), b);
                        wc1 = c; ws1 = -s;
                    }
                    if (wc2 != 1.f || ws2 != 0.f) {
                        if (ql) { ROT23(wc2, ws2); } else { MROTA(wc2, ws2); }
                    }
                    if (wc1 != 1.f || ws1 != 0.f) {
                        if (ql) { ROT12(wc1, ws1); } else { MROTB(wc1, ws1); }
                    }
                    vd1 = FSUB(vd1, p);
                    ve1 = g;
                    continue;
                }
                // lv == 2
                if (small_e2(ve2, vd2, vd3)) { ve2 = 0.f; break; }
                {
                    float rt1, rt2, c, s;
                    if (ql) {
                        slaev2f(vd2, ve2, vd3, rt1, rt2, c, s);
                        ROT23(c, s);
                        vd2 = rt1; vd3 = rt2;
                    } else {
                        slaev2f(vd3, ve2, vd2, rt1, rt2, c, s);
                        ROT12(c, s);
                        vd3 = rt1; vd2 = rt2;
                    }
                    ve2 = 0.f;
                }
                break;
            }
            if (ql) { d1 = vd1; d2 = vd2; d3 = vd3; }
            else    { d3 = vd1; d2 = vd2; d1 = vd3; }
        }
    } else if (blk12) {
        // ----- block [1,2] -----
        float anorm = fmaxf(fmaxf(fabsf(d1), fabsf(d2)), fabsf(e1));
        if (anorm != 0.f) {
            bool qlb = !(fabsf(d2) < fabsf(d1));
            bool sml = qlb ? small_e2(e1, d1, d2) : small_e2(e1, d2, d1);
            if (sml) {
                e1 = 0.f;
            } else {
                float rt1, rt2, c, s;
                slaev2f(d1, e1, d2, rt1, rt2, c, s);
                ROT12(c, s);
                d1 = rt1; d2 = rt2; e1 = 0.f;
            }
        }
    } else if (blk23) {
        // ----- block [2,3] -----
        float anorm = fmaxf(fmaxf(fabsf(d2), fabsf(d3)), fabsf(e2));
        if (anorm != 0.f) {
            bool qlb = !(fabsf(d3) < fabsf(d2));
            bool sml = qlb ? small_e2(e2, d2, d3) : small_e2(e2, d3, d2);
            if (sml) {
                e2 = 0.f;
            } else {
                float rt1, rt2, c, s;
                slaev2f(d2, e2, d3, rt1, rt2, c, s);
                ROT23(c, s);
                d2 = rt1; d3 = rt2; e2 = 0.f;
            }
        }
    }

    // selection sort (ascending, column swaps)
    {
        int kk = 1; float p = d1;
        if (d2 < p) { kk = 2; p = d2; }
        if (d3 < p) { kk = 3; p = d3; }
        if (kk == 2) { d2 = d1; d1 = p; SWAPC12(); }
        else if (kk == 3) { d3 = d1; d1 = p; SWAPC13(); }
    }
    {
        if (d3 < d2) { float p = d2; d2 = d3; d3 = p; SWAPC23(); }
    }

    // SORMTR: Z := H(1)*Z
    if (tau1 != 0.f) {
        float w, tt;
        w = FADD(z21, FMUL(z31, v3)); tt = FMUL(-tau1, w);
        z21 = FADD(z21, tt); z31 = FADD(z31, FMUL(v3, tt));
        w = FADD(z22, FMUL(z32, v3)); tt = FMUL(-tau1, w);
        z22 = FADD(z22, tt); z32 = FADD(z32, FMUL(v3, tt));
        w = FADD(z23, FMUL(z33, v3)); tt = FMUL(-tau1, w);
        z23 = FADD(z23, tt); z33 = FADD(z33, FMUL(v3, tt));
    }

    float* o = out + (long long)ogi * 9;
    o[0] = z11; o[1] = z21; o[2] = z31;
    o[3] = z12; o[4] = z22; o[5] = z32;
    o[6] = z13; o[7] = z23; o[8] = z33;
}

// ---------------------------------------------------------------------------
// Launch
// ---------------------------------------------------------------------------
extern "C" void kernel_launch(void* const* d_in, const int* in_sizes, int n_in,
                              void* d_out, int out_size) {
    const float* pos = (const float*)d_in[0];
    const int* edge_src = (const int*)d_in[1];
    // d_in[2] = edge_dst: unused (edge_dst == repeat(arange(n), k))
    const int* num_neighbors = (const int*)d_in[3];

    int n = in_sizes[3];
    int k = in_sizes[1] / n;

    pad_kernel<<<(n + 255) / 256, 256>>>(pos, n);
    fused_kernel<<<(n + BLK - 1) / BLK, BLK>>>(edge_src, num_neighbors,
                                               (float*)d_out, n, k);
}